// round 5
// baseline (speedup 1.0000x reference)
#include <cuda_runtime.h>
#include <cstdint>
#include <cstddef>

// ---------------------------------------------------------------------------
// 50-layer LSTM, persistent wavefront kernel, tf32 mma.sync.
//   B=64, T=256, D=H=256, L=50, O=2
// Layout choices:
//   g_h[l][t+1][b][h]   : layer outputs, slot 0 is h_{-1}=0
//   g_wfrag             : weights pre-swizzled into mma B-fragment order,
//                         columns permuted n_local = 4*unit + gate
//   progress flags      : st.release / ld.acquire, one per (layer, cta)
// ---------------------------------------------------------------------------

#define LAYERS 50
#define BATCH  64
#define TSTEPS 256
#define HID    256
#define GPL    2                 // CTAs per layer
#define NCTA   (LAYERS*GPL)      // 100 persistent CTAs (<=148 SMs -> coresident)

// per-(l,cta,wn) fragment block: 64 ktiles * 16 ntiles * 64 floats
#define WFRAG_PER_WARP (64*16*64)
#define HSLOT (BATCH*HID)                    // 16384 floats per time slot
#define HLAYER ((size_t)(TSTEPS+1)*HSLOT)    // 257 slots per layer

__device__ float    g_h[(size_t)LAYERS*HLAYER];                    // ~843 MB
__device__ float    g_wfrag[(size_t)LAYERS*2*4*WFRAG_PER_WARP];    // ~105 MB
__device__ float    g_bias[LAYERS*1024];
__device__ unsigned g_prog[128];

// ------------------------------- helpers -----------------------------------

__device__ __forceinline__ uint32_t f2tf32(float f) {
    uint32_t u;
    asm("cvt.rna.tf32.f32 %0, %1;" : "=r"(u) : "f"(f));
    return u;
}
__device__ __forceinline__ unsigned ld_acq(const unsigned* p) {
    unsigned v;
    asm volatile("ld.acquire.gpu.u32 %0, [%1];" : "=r"(v) : "l"(p) : "memory");
    return v;
}
__device__ __forceinline__ void st_rel(unsigned* p, unsigned v) {
    asm volatile("st.release.gpu.u32 [%0], %1;" :: "l"(p), "r"(v) : "memory");
}
__device__ __forceinline__ void mma8(float acc[4], const uint32_t a[4],
                                     uint32_t b0, uint32_t b1) {
    asm("mma.sync.aligned.m16n8k8.row.col.f32.tf32.tf32.f32 "
        "{%0,%1,%2,%3},{%4,%5,%6,%7},{%8,%9},{%0,%1,%2,%3};"
        : "+f"(acc[0]), "+f"(acc[1]), "+f"(acc[2]), "+f"(acc[3])
        : "r"(a[0]), "r"(a[1]), "r"(a[2]), "r"(a[3]), "r"(b0), "r"(b1));
}
__device__ __forceinline__ float sigm(float x) {
    return __fdividef(1.f, 1.f + __expf(-x));
}
__device__ __forceinline__ float tanh_f(float x) {
    float ax = fabsf(x);
    float e  = __expf(-2.f * ax);
    float r  = __fdividef(1.f - e, 1.f + e);
    return copysignf(r, x);
}

// ------------------------------ prep kernels --------------------------------

// Swizzle W_ih|W_hh into mma B-fragment order, pre-rounded to tf32.
// Linear index decomposition: [l][g][wn][ktile][ntile][e(64)], e=(thread,j).
__global__ void prep_wfrag(const float* __restrict__ Wih,
                           const float* __restrict__ Whh) {
    size_t idx = (size_t)blockIdx.x * 256 + threadIdx.x;
    int e     = (int)(idx & 63);
    int ntile = (int)((idx >> 6)  & 15);
    int ktile = (int)((idx >> 10) & 63);
    int wn    = (int)((idx >> 16) & 3);
    int gg    = (int)((idx >> 18) & 1);
    int l     = (int)(idx >> 19);
    if (l >= LAYERS) return;
    int th = e >> 1, j = e & 1;
    int col  = th >> 2;
    int krow = (th & 3) + j * 4;
    int nloc = wn * 128 + ntile * 8 + col;   // column within CTA's 512
    int u    = nloc >> 2;                    // hidden-unit (0..127)
    int gate = nloc & 3;                     // i,f,g,o
    int r    = gate * 256 + gg * 128 + u;    // original row in [4H]
    int k    = ktile * 8 + krow;             // 0..511 : [x | h]
    float v = (k < 256) ? Wih[((size_t)l * 1024 + r) * 256 + k]
                        : Whh[((size_t)l * 1024 + r) * 256 + (k - 256)];
    g_wfrag[idx] = __uint_as_float(f2tf32(v));
}

__global__ void prep_bias_init(const float* __restrict__ bih,
                               const float* __restrict__ bhh) {
    int idx = blockIdx.x * 256 + threadIdx.x;
    if (idx < LAYERS * 1024) {
        int l = idx >> 10;
        int nl = idx & 1023;
        int gg = nl >> 9;
        int nloc = nl & 511;
        int u = nloc >> 2, gate = nloc & 3;
        int r = gate * 256 + gg * 128 + u;
        g_bias[idx] = bih[l * 1024 + r] + bhh[l * 1024 + r];
    }
    if (idx < 128) g_prog[idx] = 0;
}

__global__ void zero_h0() {
    float* p = g_h + (size_t)blockIdx.x * HLAYER;   // slot 0 = h_{-1}
    for (int i = threadIdx.x; i < HSLOT; i += 256) p[i] = 0.f;
}

// --------------------------- persistent LSTM --------------------------------

__global__ void __launch_bounds__(256, 1)
lstm_persistent(const float* __restrict__ x) {
    const int l   = blockIdx.x / GPL;
    const int gg  = blockIdx.x % GPL;
    const int tid = threadIdx.x;
    const int lane = tid & 31;
    const int warp = tid >> 5;
    const int wm = warp >> 2;        // 0..1 : M half
    const int wn = warp & 3;         // 0..3 : 32-unit group

    __shared__ float cbuf[64 * 130];  // c-state, padded stride (conflict-free)
    __shared__ float sbias[512];

    for (int i = tid; i < 512; i += 256)
        sbias[i] = g_bias[(l * GPL + gg) * 512 + i];
    for (int i = tid; i < 64 * 130; i += 256) cbuf[i] = 0.f;
    __syncthreads();

    const float2* wbase2 = (const float2*)(g_wfrag +
        (size_t)((l * GPL + gg) * 4 + wn) * WFRAG_PER_WARP);
    float* hlayer = g_h + (size_t)l * HLAYER;
    const float* xlayer = (l == 0) ? x : (g_h + (size_t)(l - 1) * HLAYER);
    const size_t xrs = (l == 0) ? (size_t)TSTEPS * 256 : 256;  // row stride

    const int r0 = wm * 32 + (lane >> 2);
    const int q  = lane & 3;

    float acc[2][16][4];

    for (int t = 0; t < TSTEPS; ++t) {
        // ---- wait for dependencies ----
        if (tid == 0) {
            if (l > 0) {
                const unsigned need = (unsigned)(t + 1);
                while (ld_acq(&g_prog[(l - 1) * GPL]) < need ||
                       ld_acq(&g_prog[(l - 1) * GPL + 1]) < need)
                    __nanosleep(64);
            }
            if (t > 0) {
                while (ld_acq(&g_prog[l * GPL + (gg ^ 1)]) < (unsigned)t)
                    __nanosleep(64);
            }
        }
        __syncthreads();

        // xp points at x_t of this layer; hp at h_{t-1}
        const float* xp = (l == 0) ? (x + (size_t)t * 256)
                                   : (xlayer + (size_t)(t + 1) * HSLOT);
        const float* hp = hlayer + (size_t)t * HSLOT;

        // ---- init accumulators with bias ----
        #pragma unroll
        for (int j = 0; j < 16; ++j) {
            float b0 = sbias[wn * 128 + j * 8 + q * 2];
            float b1 = sbias[wn * 128 + j * 8 + q * 2 + 1];
            acc[0][j][0] = b0; acc[0][j][1] = b1; acc[0][j][2] = b0; acc[0][j][3] = b1;
            acc[1][j][0] = b0; acc[1][j][1] = b1; acc[1][j][2] = b0; acc[1][j][3] = b1;
        }

        // ---- GEMM: gates += [x_t | h_{t-1}] @ Wc^T  (K = 512, tf32 mma) ----
        #pragma unroll 1
        for (int ktile = 0; ktile < 64; ++ktile) {
            const int kk = (ktile << 3) + q;
            const float* s;
            size_t rs;
            int ko;
            if (kk < 256) { s = xp; rs = xrs; ko = kk; }
            else          { s = hp; rs = 256; ko = kk - 256; }
            uint32_t A0[4], A1[4];
            A0[0] = f2tf32(__ldg(s + (size_t)(r0     ) * rs + ko));
            A0[1] = f2tf32(__ldg(s + (size_t)(r0 +  8) * rs + ko));
            A0[2] = f2tf32(__ldg(s + (size_t)(r0     ) * rs + ko + 4));
            A0[3] = f2tf32(__ldg(s + (size_t)(r0 +  8) * rs + ko + 4));
            A1[0] = f2tf32(__ldg(s + (size_t)(r0 + 16) * rs + ko));
            A1[1] = f2tf32(__ldg(s + (size_t)(r0 + 24) * rs + ko));
            A1[2] = f2tf32(__ldg(s + (size_t)(r0 + 16) * rs + ko + 4));
            A1[3] = f2tf32(__ldg(s + (size_t)(r0 + 24) * rs + ko + 4));

            const float2* wk = wbase2 + (size_t)ktile * 512 + lane;
            #pragma unroll
            for (int j = 0; j < 16; ++j) {
                float2 bv = __ldg(wk + j * 32);
                uint32_t b0 = __float_as_uint(bv.x);
                uint32_t b1 = __float_as_uint(bv.y);
                mma8(acc[0][j], A0, b0, b1);
                mma8(acc[1][j], A1, b0, b1);
            }
        }

        // ---- elementwise LSTM update ----
        // Column permutation means each thread quad holds (i,f)/(g,o) pairs of
        // one unit; one shfl_xor(1) completes the gate set.
        float* hout = hlayer + (size_t)(t + 1) * HSLOT;
        #pragma unroll
        for (int mt = 0; mt < 2; ++mt) {
            #pragma unroll
            for (int j = 0; j < 16; ++j) {
                float a0 = acc[mt][j][0], a1 = acc[mt][j][1];
                float a2 = acc[mt][j][2], a3 = acc[mt][j][3];
                float p0 = __shfl_xor_sync(0xffffffffu, a0, 1);
                float p1 = __shfl_xor_sync(0xffffffffu, a1, 1);
                float p2 = __shfl_xor_sync(0xffffffffu, a2, 1);
                float p3 = __shfl_xor_sync(0xffffffffu, a3, 1);
                if (!(lane & 1)) {            // even lanes hold (i,f); partner (g,o)
                    int u   = wn * 32 + j * 2 + (q >> 1);
                    int row = wm * 32 + mt * 16 + (lane >> 2);
                    int hcol = gg * 128 + u;
                    {
                        float i_ = sigm(a0), f_ = sigm(a1);
                        float g_ = tanh_f(p0), o_ = sigm(p1);
                        float c  = cbuf[row * 130 + u];
                        float cn = fmaf(f_, c, i_ * g_);
                        cbuf[row * 130 + u] = cn;
                        hout[row * HID + hcol] = o_ * tanh_f(cn);
                    }
                    {
                        int row2 = row + 8;
                        float i_ = sigm(a2), f_ = sigm(a3);
                        float g_ = tanh_f(p2), o_ = sigm(p3);
                        float c  = cbuf[row2 * 130 + u];
                        float cn = fmaf(f_, c, i_ * g_);
                        cbuf[row2 * 130 + u] = cn;
                        hout[row2 * HID + hcol] = o_ * tanh_f(cn);
                    }
                }
            }
        }

        __threadfence();
        __syncthreads();
        if (tid == 0) st_rel(&g_prog[l * GPL + gg], (unsigned)(t + 1));
    }
}

// ------------------------------ output head ---------------------------------

__global__ void out_proj(const float* __restrict__ Wout,
                         const float* __restrict__ bout,
                         float* __restrict__ out) {
    int p = blockIdx.x * 8 + (threadIdx.x >> 5);   // (t*64+b), 16384 total
    int lane = threadIdx.x & 31;
    int t = p >> 6, b = p & 63;
    const float* h = g_h + (size_t)(LAYERS - 1) * HLAYER +
                     (size_t)(t + 1) * HSLOT + (size_t)b * HID;
    const float4* h4 = (const float4*)(h + lane * 8);
    const float4* w0 = (const float4*)(Wout + lane * 8);
    const float4* w1 = (const float4*)(Wout + 256 + lane * 8);
    float4 hv0 = h4[0], hv1 = h4[1];
    float4 a = w0[0], b4 = w0[1], c = w1[0], d = w1[1];
    float s0 = hv0.x*a.x + hv0.y*a.y + hv0.z*a.z + hv0.w*a.w
             + hv1.x*b4.x + hv1.y*b4.y + hv1.z*b4.z + hv1.w*b4.w;
    float s1 = hv0.x*c.x + hv0.y*c.y + hv0.z*c.z + hv0.w*c.w
             + hv1.x*d.x + hv1.y*d.y + hv1.z*d.z + hv1.w*d.w;
    #pragma unroll
    for (int off = 16; off > 0; off >>= 1) {
        s0 += __shfl_xor_sync(0xffffffffu, s0, off);
        s1 += __shfl_xor_sync(0xffffffffu, s1, off);
    }
    if (lane == 0) {
        out[(size_t)b * (TSTEPS * 2) + t * 2 + 0] = sigm(s0 + bout[0]);
        out[(size_t)b * (TSTEPS * 2) + t * 2 + 1] = sigm(s1 + bout[1]);
    }
}

// ------------------------------- launcher -----------------------------------

extern "C" void kernel_launch(void* const* d_in, const int* in_sizes, int n_in,
                              void* d_out, int out_size) {
    const float* x    = (const float*)d_in[0];
    const float* Wih  = (const float*)d_in[1];
    const float* Whh  = (const float*)d_in[2];
    const float* bih  = (const float*)d_in[3];
    const float* bhh  = (const float*)d_in[4];
    const float* Wout = (const float*)d_in[5];
    const float* bout = (const float*)d_in[6];
    float* out = (float*)d_out;

    prep_wfrag<<<102400, 256>>>(Wih, Whh);      // 26.2M fragment elements
    prep_bias_init<<<200, 256>>>(bih, bhh);     // bias permute + progress reset
    zero_h0<<<LAYERS, 256>>>();                 // h_{-1} = 0 slots
    lstm_persistent<<<NCTA, 256>>>(x);          // 100 coresident CTAs
    out_proj<<<2048, 256>>>(Wout, bout, out);   // final sigmoid head
}

// round 6
// speedup vs baseline: 3.1724x; 3.1724x over previous
#include <cuda_runtime.h>
#include <cuda_fp16.h>
#include <cstdint>
#include <cstddef>

// ---------------------------------------------------------------------------
// 50-layer LSTM, persistent wavefront, fp16 m16n8k16 mma.sync.
//   B=64, T=256, D=H=256, L=50, O=2
//   - g_h16[l][t+1][b][h] fp16 layer outputs (slot 0 = h_{-1} = 0)
//   - g_w16: weights pre-swizzled into packed B-fragment order (uint4 loads),
//            columns permuted nloc = 4*unit + gate
//   - per step: stage [x_t | h_{t-1}] into SMEM fp16, ldmatrix A frags
//   - 512 threads (16 warps); warp w owns cols 32w..32w+31 (8 full units)
// ---------------------------------------------------------------------------

#define LAYERS 50
#define TSTEPS 256
#define GPL    2
#define NCTA   (LAYERS*GPL)                // 100 persistent CTAs, all resident
#define HSLOT  16384                       // 64*256 halves per time slot
#define HLAYER ((size_t)(TSTEPS+1)*HSLOT)

#define SA_STRIDE 520                      // halves per SMEM A row (conflict-free)
#define W_WARP_HALVES (32*2*32*8)          // 16384 halves per (l,gg,warp)
#define SMEM_BYTES (64*132*4 + 64*SA_STRIDE*2 + 512*4)   // 102400

__device__ __half   g_h16[(size_t)LAYERS*HLAYER];                 // ~421 MB
__device__ __half   g_w16[(size_t)LAYERS*2*16*W_WARP_HALVES];     // ~52 MB
__device__ float    g_bias[LAYERS*1024];
__device__ unsigned g_prog[128];

// ------------------------------- helpers -----------------------------------

__device__ __forceinline__ unsigned ld_acq(const unsigned* p) {
    unsigned v;
    asm volatile("ld.acquire.gpu.u32 %0, [%1];" : "=r"(v) : "l"(p) : "memory");
    return v;
}
__device__ __forceinline__ void st_rel(unsigned* p, unsigned v) {
    asm volatile("st.release.gpu.u32 [%0], %1;" :: "l"(p), "r"(v) : "memory");
}
__device__ __forceinline__ void mma16(float* acc, const uint32_t a[4],
                                      uint32_t b0, uint32_t b1) {
    asm("mma.sync.aligned.m16n8k16.row.col.f32.f16.f16.f32 "
        "{%0,%1,%2,%3},{%4,%5,%6,%7},{%8,%9},{%0,%1,%2,%3};"
        : "+f"(acc[0]), "+f"(acc[1]), "+f"(acc[2]), "+f"(acc[3])
        : "r"(a[0]), "r"(a[1]), "r"(a[2]), "r"(a[3]), "r"(b0), "r"(b1));
}
__device__ __forceinline__ void ldsm4(uint32_t r[4], uint32_t saddr) {
    asm volatile("ldmatrix.sync.aligned.m8n8.x4.shared.b16 {%0,%1,%2,%3}, [%4];"
        : "=r"(r[0]), "=r"(r[1]), "=r"(r[2]), "=r"(r[3]) : "r"(saddr));
}
__device__ __forceinline__ float sigm(float x) {
    return __fdividef(1.f, 1.f + __expf(-x));
}
__device__ __forceinline__ float tanh_f(float x) {
    float ax = fabsf(x);
    float e  = __expf(-2.f * ax);
    float r  = __fdividef(1.f - e, 1.f + e);
    return copysignf(r, x);
}

// ------------------------------ prep kernels --------------------------------

// Pack weights into uint4-loadable fp16 B fragments.
// half index: [l][gg][w(16)][kt(32)][np(2)][lane(32)][h(8)]
// within the 16B chunk: jj=h>>1 selects (b0 nt0, b1 nt0, b0 nt1, b1 nt1)
__global__ void prep_wfrag16(const float* __restrict__ Wih,
                             const float* __restrict__ Whh) {
    size_t idx = (size_t)blockIdx.x * 256 + threadIdx.x;
    int h    = (int)(idx & 7);
    int lane = (int)((idx >> 3)  & 31);
    int np   = (int)((idx >> 8)  & 1);
    int kt   = (int)((idx >> 9)  & 31);
    int w    = (int)((idx >> 14) & 15);
    int gg   = (int)((idx >> 18) & 1);
    int l    = (int)(idx >> 19);
    if (l >= LAYERS) return;
    int jj = h >> 1, hb = h & 1;
    int n  = w * 32 + np * 16 + (jj >> 1) * 8 + (lane >> 2);
    int k  = kt * 16 + (lane & 3) * 2 + hb + (jj & 1) * 8;
    int u = n >> 2, gate = n & 3;
    int r = gate * 256 + gg * 128 + u;
    float v = (k < 256) ? Wih[((size_t)l * 1024 + r) * 256 + k]
                        : Whh[((size_t)l * 1024 + r) * 256 + (k - 256)];
    g_w16[idx] = __float2half(v);
}

__global__ void prep_bias_init(const float* __restrict__ bih,
                               const float* __restrict__ bhh) {
    int idx = blockIdx.x * 256 + threadIdx.x;
    if (idx < LAYERS * 1024) {
        int l = idx >> 10;
        int nl = idx & 1023;
        int gg = nl >> 9;
        int nloc = nl & 511;
        int u = nloc >> 2, gate = nloc & 3;
        int r = gate * 256 + gg * 128 + u;
        g_bias[idx] = bih[l * 1024 + r] + bhh[l * 1024 + r];
    }
    if (idx < 128) g_prog[idx] = 0;
}

__global__ void zero_h0() {
    uint4* p = (uint4*)(g_h16 + (size_t)blockIdx.x * HLAYER);  // slot 0
    for (int i = threadIdx.x; i < 2048; i += 256)
        p[i] = make_uint4(0u, 0u, 0u, 0u);
}

// --------------------------- persistent LSTM --------------------------------

__global__ void __launch_bounds__(512, 1)
lstm_persistent(const float* __restrict__ x) {
    extern __shared__ char smem[];
    float*  cbuf  = (float*)smem;                                   // 64*132
    __half* sA    = (__half*)(smem + 64 * 132 * 4);                 // 64*520
    float*  sbias = (float*)(smem + 64 * 132 * 4 + 64 * SA_STRIDE * 2);

    const int l    = blockIdx.x >> 1;
    const int gg   = blockIdx.x & 1;
    const int tid  = threadIdx.x;
    const int lane = tid & 31;
    const int w    = tid >> 5;      // 0..15
    const int q    = lane & 3;

    for (int i = tid; i < 512; i += 512)
        sbias[i] = g_bias[(l * GPL + gg) * 512 + i];
    for (int i = tid; i < 64 * 132; i += 512) cbuf[i] = 0.f;
    __syncthreads();

    const uint4* wv = (const uint4*)(g_w16 +
        (size_t)((l * GPL + gg) * 16 + w) * W_WARP_HALVES);
    __half* hlayer = g_h16 + (size_t)l * HLAYER;
    const __half* hprev = (l > 0) ? (g_h16 + (size_t)(l - 1) * HLAYER) : nullptr;

    uint32_t sA_base = (uint32_t)__cvta_generic_to_shared(sA);
    const int rowA = lane & 15;
    const int kofA = (lane >> 4) * 8;

    float acc[4][4][4];

    for (int t = 0; t < TSTEPS; ++t) {
        // ---- wait for dependencies ----
        if (tid == 0) {
            if (l > 0) {
                const unsigned need = (unsigned)(t + 1);
                while (ld_acq(&g_prog[(l - 1) * GPL]) < need ||
                       ld_acq(&g_prog[(l - 1) * GPL + 1]) < need)
                    __nanosleep(64);
            }
            if (t > 0) {
                while (ld_acq(&g_prog[l * GPL + (gg ^ 1)]) < (unsigned)t)
                    __nanosleep(64);
            }
        }
        __syncthreads();

        // ---- stage A = [x_t | h_{t-1}] into SMEM (fp16) ----
        if (l == 0) {
            #pragma unroll
            for (int i = tid; i < 4096; i += 512) {       // 64 rows * 64 float4
                int row = i >> 6, c4 = i & 63;
                float4 v = __ldg((const float4*)(x +
                              ((size_t)row * TSTEPS + t) * 256) + c4);
                __half2* dst = (__half2*)(sA + row * SA_STRIDE + c4 * 4);
                dst[0] = __floats2half2_rn(v.x, v.y);
                dst[1] = __floats2half2_rn(v.z, v.w);
            }
        } else {
            const uint4* src = (const uint4*)(hprev + (size_t)(t + 1) * HSLOT);
            #pragma unroll
            for (int i = tid; i < 2048; i += 512) {       // 64 rows * 32 uint4
                int row = i >> 5, c8 = i & 31;
                *(uint4*)(sA + row * SA_STRIDE + c8 * 8) = __ldg(src + i);
            }
        }
        {
            const uint4* src = (const uint4*)(hlayer + (size_t)t * HSLOT);
            #pragma unroll
            for (int i = tid; i < 2048; i += 512) {
                int row = i >> 5, c8 = i & 31;
                *(uint4*)(sA + row * SA_STRIDE + 256 + c8 * 8) = __ldg(src + i);
            }
        }
        __syncthreads();

        // ---- init accumulators with bias ----
        #pragma unroll
        for (int nt = 0; nt < 4; ++nt) {
            float b0 = sbias[w * 32 + nt * 8 + q * 2];
            float b1 = sbias[w * 32 + nt * 8 + q * 2 + 1];
            #pragma unroll
            for (int mt = 0; mt < 4; ++mt) {
                acc[mt][nt][0] = b0; acc[mt][nt][1] = b1;
                acc[mt][nt][2] = b0; acc[mt][nt][3] = b1;
            }
        }

        // ---- GEMM: gates += A[64,512] @ Wc^T, fp16 mma, B prefetched ----
        uint4 bb0 = __ldg(wv + lane);
        uint4 bb1 = __ldg(wv + 32 + lane);
        #pragma unroll 2
        for (int kt = 0; kt < 32; ++kt) {
            uint4 nb0, nb1;
            if (kt < 31) {
                nb0 = __ldg(wv + (kt + 1) * 64 + lane);
                nb1 = __ldg(wv + (kt + 1) * 64 + 32 + lane);
            }
            uint32_t av[4][4];
            #pragma unroll
            for (int mt = 0; mt < 4; ++mt) {
                uint32_t addr = sA_base +
                    (uint32_t)(((mt * 16 + rowA) * SA_STRIDE + kt * 16 + kofA) * 2);
                ldsm4(av[mt], addr);
            }
            #pragma unroll
            for (int mt = 0; mt < 4; ++mt) {
                mma16(acc[mt][0], av[mt], bb0.x, bb0.y);
                mma16(acc[mt][1], av[mt], bb0.z, bb0.w);
                mma16(acc[mt][2], av[mt], bb1.x, bb1.y);
                mma16(acc[mt][3], av[mt], bb1.z, bb1.w);
            }
            if (kt < 31) { bb0 = nb0; bb1 = nb1; }
        }

        // ---- elementwise LSTM update ----
        // thread quad: q∈{0,2} holds (i,f), partner q^1 holds (g,o); one shfl.
        __half* hout = hlayer + (size_t)(t + 1) * HSLOT + gg * 128;
        #pragma unroll
        for (int mt = 0; mt < 4; ++mt) {
            #pragma unroll
            for (int nt = 0; nt < 4; ++nt) {
                float a0 = acc[mt][nt][0], a1 = acc[mt][nt][1];
                float a2 = acc[mt][nt][2], a3 = acc[mt][nt][3];
                float p0 = __shfl_xor_sync(0xffffffffu, a0, 1);
                float p1 = __shfl_xor_sync(0xffffffffu, a1, 1);
                float p2 = __shfl_xor_sync(0xffffffffu, a2, 1);
                float p3 = __shfl_xor_sync(0xffffffffu, a3, 1);
                if (!(lane & 1)) {
                    int u   = w * 8 + nt * 2 + (q >> 1);
                    int row = mt * 16 + (lane >> 2);
                    {
                        float i_ = sigm(a0), f_ = sigm(a1);
                        float g_ = tanh_f(p0), o_ = sigm(p1);
                        float c  = cbuf[row * 132 + u];
                        float cn = fmaf(f_, c, i_ * g_);
                        cbuf[row * 132 + u] = cn;
                        hout[(size_t)row * 256 + u] = __float2half(o_ * tanh_f(cn));
                    }
                    {
                        int row2 = row + 8;
                        float i_ = sigm(a2), f_ = sigm(a3);
                        float g_ = tanh_f(p2), o_ = sigm(p3);
                        float c  = cbuf[row2 * 132 + u];
                        float cn = fmaf(f_, c, i_ * g_);
                        cbuf[row2 * 132 + u] = cn;
                        hout[(size_t)row2 * 256 + u] = __float2half(o_ * tanh_f(cn));
                    }
                }
            }
        }

        __threadfence();
        __syncthreads();
        if (tid == 0) st_rel(&g_prog[l * GPL + gg], (unsigned)(t + 1));
    }
}

// ------------------------------ output head ---------------------------------

__global__ void out_proj(const float* __restrict__ Wout,
                         const float* __restrict__ bout,
                         float* __restrict__ out) {
    int p = blockIdx.x * 8 + (threadIdx.x >> 5);   // (t*64+b), 16384 total
    int lane = threadIdx.x & 31;
    int t = p >> 6, b = p & 63;
    const __half* h = g_h16 + (size_t)(LAYERS - 1) * HLAYER +
                      (size_t)(t + 1) * HSLOT + (size_t)b * 256 + lane * 8;
    uint4 hv = *(const uint4*)h;
    const __half2* hh = (const __half2*)&hv;
    const float* w0 = Wout + lane * 8;
    const float* w1 = Wout + 256 + lane * 8;
    float s0 = 0.f, s1 = 0.f;
    #pragma unroll
    for (int j = 0; j < 4; ++j) {
        float2 f = __half22float2(hh[j]);
        s0 += f.x * w0[2 * j] + f.y * w0[2 * j + 1];
        s1 += f.x * w1[2 * j] + f.y * w1[2 * j + 1];
    }
    #pragma unroll
    for (int off = 16; off > 0; off >>= 1) {
        s0 += __shfl_xor_sync(0xffffffffu, s0, off);
        s1 += __shfl_xor_sync(0xffffffffu, s1, off);
    }
    if (lane == 0) {
        out[(size_t)b * (TSTEPS * 2) + t * 2 + 0] = sigm(s0 + bout[0]);
        out[(size_t)b * (TSTEPS * 2) + t * 2 + 1] = sigm(s1 + bout[1]);
    }
}

// ------------------------------- launcher -----------------------------------

extern "C" void kernel_launch(void* const* d_in, const int* in_sizes, int n_in,
                              void* d_out, int out_size) {
    const float* x    = (const float*)d_in[0];
    const float* Wih  = (const float*)d_in[1];
    const float* Whh  = (const float*)d_in[2];
    const float* bih  = (const float*)d_in[3];
    const float* bhh  = (const float*)d_in[4];
    const float* Wout = (const float*)d_in[5];
    const float* bout = (const float*)d_in[6];
    float* out = (float*)d_out;

    cudaFuncSetAttribute(lstm_persistent,
                         cudaFuncAttributeMaxDynamicSharedMemorySize, SMEM_BYTES);

    prep_wfrag16<<<102400, 256>>>(Wih, Whh);    // 26.2M packed fp16 fragments
    prep_bias_init<<<200, 256>>>(bih, bhh);     // bias permute + progress reset
    zero_h0<<<LAYERS, 256>>>();                 // h_{-1} = 0 slots (fp16)
    lstm_persistent<<<NCTA, 512, SMEM_BYTES>>>(x);
    out_proj<<<2048, 256>>>(Wout, bout, out);   // final sigmoid head
}

// round 7
// speedup vs baseline: 3.3693x; 1.0620x over previous
#include <cuda_runtime.h>
#include <cuda_fp16.h>
#include <cstdint>
#include <cstddef>

// ---------------------------------------------------------------------------
// 50-layer LSTM, persistent wavefront, fp16 m16n8k16 mma.sync, K-split.
//   B=64, T=256, D=H=256, L=50, O=2
//   - gates = bias + A_h @ W_h (own-layer dep only) + A_x @ W_x (prev layer)
//     -> h-half GEMM runs BEFORE the cross-layer wait (hides handoff)
//   - warp tile 32 rows x 64 cols: halves LDSM (A) smem traffic
//   - all-lane elementwise via gate-parity pairing + shfl_xor(1)
// ---------------------------------------------------------------------------

#define LAYERS 50
#define TSTEPS 256
#define GPL    2
#define NCTA   (LAYERS*GPL)                // 100 persistent CTAs, all resident
#define HSLOT  16384                       // 64*256 halves per time slot
#define HLAYER ((size_t)(TSTEPS+1)*HSLOT)

#define SA_STRIDE 520                      // halves per SMEM A row
#define W_WARP_HALVES 32768                // per (l,gg,wn): 32kt*4j*32lane*8h
#define SMEM_BYTES (64*130*4 + 64*SA_STRIDE*2 + 512*4)   // 101888

__device__ __half   g_h16[(size_t)LAYERS*HLAYER];                 // ~421 MB
__device__ __half   g_w16[(size_t)LAYERS*2*8*W_WARP_HALVES];      // ~52 MB
__device__ float    g_bias[LAYERS*1024];
__device__ unsigned g_prog[128];

// ------------------------------- helpers -----------------------------------

__device__ __forceinline__ unsigned ld_acq(const unsigned* p) {
    unsigned v;
    asm volatile("ld.acquire.gpu.u32 %0, [%1];" : "=r"(v) : "l"(p) : "memory");
    return v;
}
__device__ __forceinline__ unsigned long long ld_acq64(const unsigned* p) {
    unsigned long long v;
    asm volatile("ld.acquire.gpu.u64 %0, [%1];" : "=l"(v) : "l"(p) : "memory");
    return v;
}
__device__ __forceinline__ void st_rel(unsigned* p, unsigned v) {
    asm volatile("st.release.gpu.u32 [%0], %1;" :: "l"(p), "r"(v) : "memory");
}
__device__ __forceinline__ void mma16(float* acc, const uint32_t a[4],
                                      uint32_t b0, uint32_t b1) {
    asm("mma.sync.aligned.m16n8k16.row.col.f32.f16.f16.f32 "
        "{%0,%1,%2,%3},{%4,%5,%6,%7},{%8,%9},{%0,%1,%2,%3};"
        : "+f"(acc[0]), "+f"(acc[1]), "+f"(acc[2]), "+f"(acc[3])
        : "r"(a[0]), "r"(a[1]), "r"(a[2]), "r"(a[3]), "r"(b0), "r"(b1));
}
__device__ __forceinline__ void ldsm4(uint32_t r[4], uint32_t saddr) {
    asm volatile("ldmatrix.sync.aligned.m8n8.x4.shared.b16 {%0,%1,%2,%3}, [%4];"
        : "=r"(r[0]), "=r"(r[1]), "=r"(r[2]), "=r"(r[3]) : "r"(saddr));
}
__device__ __forceinline__ float sigm(float x) {
    return __fdividef(1.f, 1.f + __expf(-x));
}
__device__ __forceinline__ float tanh_f(float x) {
    float ax = fabsf(x);
    float e  = __expf(-2.f * ax);
    float r  = __fdividef(1.f - e, 1.f + e);
    return copysignf(r, x);
}

// ------------------------------ prep kernels --------------------------------

// Pack weights into uint4-loadable fp16 B fragments.
// half index: [l][gg][wn(8)][kt(32)][j(4)][lane(32)][h(8)]
// uint4 j covers nt = 2j (x,y regs) and nt = 2j+1 (z,w regs).
__global__ void prep_wfrag16(const float* __restrict__ Wih,
                             const float* __restrict__ Whh) {
    size_t idx = (size_t)blockIdx.x * 256 + threadIdx.x;
    int h    = (int)(idx & 7);
    int lane = (int)((idx >> 3)  & 31);
    int j    = (int)((idx >> 8)  & 3);
    int kt   = (int)((idx >> 10) & 31);
    int wn   = (int)((idx >> 15) & 7);
    int gg   = (int)((idx >> 18) & 1);
    int l    = (int)(idx >> 19);
    if (l >= LAYERS) return;
    int jj = h >> 1, hb = h & 1;
    int nt = j * 2 + (jj >> 1);
    int n  = wn * 64 + nt * 8 + (lane >> 2);
    int k  = kt * 16 + (lane & 3) * 2 + hb + (jj & 1) * 8;
    int u = n >> 2, gate = n & 3;
    int r = gate * 256 + gg * 128 + u;
    float v = (k < 256) ? Wih[((size_t)l * 1024 + r) * 256 + k]
                        : Whh[((size_t)l * 1024 + r) * 256 + (k - 256)];
    g_w16[idx] = __float2half(v);
}

__global__ void prep_bias_init(const float* __restrict__ bih,
                               const float* __restrict__ bhh) {
    int idx = blockIdx.x * 256 + threadIdx.x;
    if (idx < LAYERS * 1024) {
        int l = idx >> 10;
        int nl = idx & 1023;
        int gg = nl >> 9;
        int nloc = nl & 511;
        int u = nloc >> 2, gate = nloc & 3;
        int r = gate * 256 + gg * 128 + u;
        g_bias[idx] = bih[l * 1024 + r] + bhh[l * 1024 + r];
    }
    if (idx < 128) g_prog[idx] = 0;
}

__global__ void zero_h0() {
    uint4* p = (uint4*)(g_h16 + (size_t)blockIdx.x * HLAYER);  // slot 0
    for (int i = threadIdx.x; i < 2048; i += 256)
        p[i] = make_uint4(0u, 0u, 0u, 0u);
}

// --------------------------- persistent LSTM --------------------------------

// one half-GEMM over k-tiles [KT0, KT0+16)
#define GEMM_HALF(KT0)                                                        \
    {                                                                         \
        uint4 bb[4];                                                          \
        _Pragma("unroll")                                                     \
        for (int jj = 0; jj < 4; ++jj)                                        \
            bb[jj] = __ldg(wv + (KT0) * 128 + jj * 32 + lane);                \
        _Pragma("unroll 4")                                                   \
        for (int kt = (KT0); kt < (KT0) + 16; ++kt) {                         \
            uint4 nb[4];                                                      \
            if (kt < (KT0) + 15) {                                            \
                _Pragma("unroll")                                             \
                for (int jj = 0; jj < 4; ++jj)                                \
                    nb[jj] = __ldg(wv + (kt + 1) * 128 + jj * 32 + lane);     \
            }                                                                 \
            uint32_t av0[4], av1[4];                                          \
            uint32_t a0 = sA_base +                                           \
                (uint32_t)((rowA * SA_STRIDE + kt * 16 + kofA) * 2);          \
            ldsm4(av0, a0);                                                   \
            ldsm4(av1, a0 + 16 * SA_STRIDE * 2);                              \
            _Pragma("unroll")                                                 \
            for (int jj = 0; jj < 4; ++jj) {                                  \
                mma16(acc[0][2*jj],   av0, bb[jj].x, bb[jj].y);               \
                mma16(acc[0][2*jj+1], av0, bb[jj].z, bb[jj].w);               \
                mma16(acc[1][2*jj],   av1, bb[jj].x, bb[jj].y);               \
                mma16(acc[1][2*jj+1], av1, bb[jj].z, bb[jj].w);               \
            }                                                                 \
            if (kt < (KT0) + 15) {                                            \
                _Pragma("unroll")                                             \
                for (int jj = 0; jj < 4; ++jj) bb[jj] = nb[jj];               \
            }                                                                 \
        }                                                                     \
    }

__global__ void __launch_bounds__(512, 1)
lstm_persistent(const float* __restrict__ x) {
    extern __shared__ char smem[];
    float*  cbuf  = (float*)smem;                                   // 64*130
    __half* sA    = (__half*)(smem + 64 * 130 * 4);                 // 64*520
    float*  sbias = (float*)(smem + 64 * 130 * 4 + 64 * SA_STRIDE * 2);

    const int l    = blockIdx.x >> 1;
    const int gg   = blockIdx.x & 1;
    const int tid  = threadIdx.x;
    const int lane = tid & 31;
    const int w    = tid >> 5;
    const int wm   = w & 1;         // M half: rows 32*wm..+32
    const int wn   = w >> 1;        // 0..7 : 64-col group
    const int q    = lane & 3;

    if (tid < 512) sbias[tid] = g_bias[(l * GPL + gg) * 512 + tid];
    for (int i = tid; i < 64 * 130; i += 512) cbuf[i] = 0.f;
    __syncthreads();

    const uint4* wv = (const uint4*)(g_w16 +
        (size_t)((l * GPL + gg) * 8 + wn) * W_WARP_HALVES);
    __half* hlayer = g_h16 + (size_t)l * HLAYER;
    const __half* hprev = (l > 0) ? (g_h16 + (size_t)(l - 1) * HLAYER) : nullptr;

    uint32_t sA_base = (uint32_t)__cvta_generic_to_shared(sA);
    const int rowA = wm * 32 + (lane & 15);
    const int kofA = (lane >> 4) * 8;
    const int odd  = lane & 1;

    float acc[2][8][4];

    for (int t = 0; t < TSTEPS; ++t) {
        // ================= phase H : own-layer dependency only =============
        if (tid == 0 && t > 0) {
            while (ld_acq(&g_prog[l * GPL + (gg ^ 1)]) < (unsigned)t)
                __nanosleep(32);
        }
        __syncthreads();

        // stage h_{t-1} -> sA cols [256,512)
        {
            const uint4* src = (const uint4*)(hlayer + (size_t)t * HSLOT);
            #pragma unroll
            for (int i = tid; i < 2048; i += 512) {
                int row = i >> 5, c8 = i & 31;
                *(uint4*)(sA + row * SA_STRIDE + 256 + c8 * 8) = __ldg(src + i);
            }
        }

        // init accumulators with bias
        #pragma unroll
        for (int nt = 0; nt < 8; ++nt) {
            float b0 = sbias[wn * 64 + nt * 8 + q * 2];
            float b1 = sbias[wn * 64 + nt * 8 + q * 2 + 1];
            acc[0][nt][0] = b0; acc[0][nt][1] = b1;
            acc[0][nt][2] = b0; acc[0][nt][3] = b1;
            acc[1][nt][0] = b0; acc[1][nt][1] = b1;
            acc[1][nt][2] = b0; acc[1][nt][3] = b1;
        }
        __syncthreads();

        GEMM_HALF(16)      // gates += h_{t-1} @ W_hh^T

        // ================= phase X : cross-layer dependency ================
        if (tid == 0 && l > 0) {
            const unsigned need = (unsigned)(t + 1);
            for (;;) {
                unsigned long long v = ld_acq64(&g_prog[(l - 1) * GPL]);
                if ((unsigned)v >= need && (unsigned)(v >> 32) >= need) break;
                __nanosleep(32);
            }
        }
        __syncthreads();

        // stage x_t -> sA cols [0,256)
        if (l == 0) {
            #pragma unroll
            for (int i = tid; i < 4096; i += 512) {       // 64 rows * 64 float4
                int row = i >> 6, c4 = i & 63;
                float4 v = __ldg((const float4*)(x +
                              ((size_t)row * TSTEPS + t) * 256) + c4);
                __half2* dst = (__half2*)(sA + row * SA_STRIDE + c4 * 4);
                dst[0] = __floats2half2_rn(v.x, v.y);
                dst[1] = __floats2half2_rn(v.z, v.w);
            }
        } else {
            const uint4* src = (const uint4*)(hprev + (size_t)(t + 1) * HSLOT);
            #pragma unroll
            for (int i = tid; i < 2048; i += 512) {
                int row = i >> 5, c8 = i & 31;
                *(uint4*)(sA + row * SA_STRIDE + c8 * 8) = __ldg(src + i);
            }
        }
        __syncthreads();

        GEMM_HALF(0)       // gates += x_t @ W_ih^T

        // ================= elementwise LSTM update =========================
        // gate parity: even-q lanes hold (i,f), odd-q hold (g,o); shfl_xor(1)
        // completes the set. Even lane updates row r, odd lane row r+8.
        __half* hout = hlayer + (size_t)(t + 1) * HSLOT + gg * 128;
        #pragma unroll
        for (int mt = 0; mt < 2; ++mt) {
            #pragma unroll
            for (int nt = 0; nt < 8; ++nt) {
                float a0 = acc[mt][nt][0], a1 = acc[mt][nt][1];
                float a2 = acc[mt][nt][2], a3 = acc[mt][nt][3];
                float p0 = __shfl_xor_sync(0xffffffffu, a0, 1);
                float p1 = __shfl_xor_sync(0xffffffffu, a1, 1);
                float p2 = __shfl_xor_sync(0xffffffffu, a2, 1);
                float p3 = __shfl_xor_sync(0xffffffffu, a3, 1);
                float vi = odd ? p2 : a0;
                float vf = odd ? p3 : a1;
                float vg = odd ? a2 : p0;
                float vo = odd ? a3 : p1;
                int u   = wn * 16 + nt * 2 + (q >> 1);
                int row = wm * 32 + mt * 16 + (lane >> 2) + (odd ? 8 : 0);
                float i_ = sigm(vi), f_ = sigm(vf);
                float g_ = tanh_f(vg), o_ = sigm(vo);
                float c  = cbuf[row * 130 + u];
                float cn = fmaf(f_, c, i_ * g_);
                cbuf[row * 130 + u] = cn;
                hout[(size_t)row * 256 + u] = __float2half(o_ * tanh_f(cn));
            }
        }

        __syncthreads();
        if (tid == 0) st_rel(&g_prog[l * GPL + gg], (unsigned)(t + 1));
    }
}

// ------------------------------ output head ---------------------------------

__global__ void out_proj(const float* __restrict__ Wout,
                         const float* __restrict__ bout,
                         float* __restrict__ out) {
    int p = blockIdx.x * 8 + (threadIdx.x >> 5);   // (t*64+b), 16384 total
    int lane = threadIdx.x & 31;
    int t = p >> 6, b = p & 63;
    const __half* h = g_h16 + (size_t)(LAYERS - 1) * HLAYER +
                      (size_t)(t + 1) * HSLOT + (size_t)b * 256 + lane * 8;
    uint4 hv = *(const uint4*)h;
    const __half2* hh = (const __half2*)&hv;
    const float* w0 = Wout + lane * 8;
    const float* w1 = Wout + 256 + lane * 8;
    float s0 = 0.f, s1 = 0.f;
    #pragma unroll
    for (int j = 0; j < 4; ++j) {
        float2 f = __half22float2(hh[j]);
        s0 += f.x * w0[2 * j] + f.y * w0[2 * j + 1];
        s1 += f.x * w1[2 * j] + f.y * w1[2 * j + 1];
    }
    #pragma unroll
    for (int off = 16; off > 0; off >>= 1) {
        s0 += __shfl_xor_sync(0xffffffffu, s0, off);
        s1 += __shfl_xor_sync(0xffffffffu, s1, off);
    }
    if (lane == 0) {
        out[(size_t)b * (TSTEPS * 2) + t * 2 + 0] = sigm(s0 + bout[0]);
        out[(size_t)b * (TSTEPS * 2) + t * 2 + 1] = sigm(s1 + bout[1]);
    }
}

// ------------------------------- launcher -----------------------------------

extern "C" void kernel_launch(void* const* d_in, const int* in_sizes, int n_in,
                              void* d_out, int out_size) {
    const float* x    = (const float*)d_in[0];
    const float* Wih  = (const float*)d_in[1];
    const float* Whh  = (const float*)d_in[2];
    const float* bih  = (const float*)d_in[3];
    const float* bhh  = (const float*)d_in[4];
    const float* Wout = (const float*)d_in[5];
    const float* bout = (const float*)d_in[6];
    float* out = (float*)d_out;

    cudaFuncSetAttribute(lstm_persistent,
                         cudaFuncAttributeMaxDynamicSharedMemorySize, SMEM_BYTES);

    prep_wfrag16<<<102400, 256>>>(Wih, Whh);    // 26.2M packed fp16 fragments
    prep_bias_init<<<200, 256>>>(bih, bhh);     // bias permute + progress reset
    zero_h0<<<LAYERS, 256>>>();                 // h_{-1} = 0 slots (fp16)
    lstm_persistent<<<NCTA, 512, SMEM_BYTES>>>(x);
    out_proj<<<2048, 256>>>(Wout, bout, out);   // final sigmoid head
}

// round 8
// speedup vs baseline: 3.6935x; 1.0962x over previous
#include <cuda_runtime.h>
#include <cuda_fp16.h>
#include <cstdint>
#include <cstddef>

// ---------------------------------------------------------------------------
// 50-layer LSTM, persistent wavefront, fp16 m16n8k16 mma.sync.
//   B=64, T=256, D=H=256, L=50, O=2
//   R8: 256 threads, warp tile 64x64 (B loaded once), gate-blocked column
//   permutation (no shuffles in elementwise), c-state in registers,
//   single merged GEMM in x-then-h order (reference-matching numerics).
//   Warp wn owns units [16wn,16wn+16); its 64 cols = [i|f|g|o] x 16 units.
// ---------------------------------------------------------------------------

#define LAYERS 50
#define TSTEPS 256
#define GPL    2
#define NCTA   (LAYERS*GPL)                // 100 persistent CTAs, all resident
#define HSLOT  16384                       // 64*256 halves per time slot
#define HLAYER ((size_t)(TSTEPS+1)*HSLOT)

#define SA_STRIDE 520                      // halves per SMEM A row
#define W_WARP_HALVES 32768                // per (l,gg,wn): 32kt*4j*32lane*8h
#define SMEM_BYTES (64*SA_STRIDE*2 + 512*4)   // 68608

__device__ __half   g_h16[(size_t)LAYERS*HLAYER];                 // ~421 MB
__device__ __half   g_w16[(size_t)LAYERS*2*8*W_WARP_HALVES];      // ~52 MB
__device__ float    g_bias[LAYERS*1024];
__device__ unsigned g_prog[128];

// ------------------------------- helpers -----------------------------------

__device__ __forceinline__ unsigned ld_acq(const unsigned* p) {
    unsigned v;
    asm volatile("ld.acquire.gpu.u32 %0, [%1];" : "=r"(v) : "l"(p) : "memory");
    return v;
}
__device__ __forceinline__ unsigned long long ld_acq64(const unsigned* p) {
    unsigned long long v;
    asm volatile("ld.acquire.gpu.u64 %0, [%1];" : "=l"(v) : "l"(p) : "memory");
    return v;
}
__device__ __forceinline__ void st_rel(unsigned* p, unsigned v) {
    asm volatile("st.release.gpu.u32 [%0], %1;" :: "l"(p), "r"(v) : "memory");
}
__device__ __forceinline__ void mma16(float* acc, const uint32_t a[4],
                                      uint32_t b0, uint32_t b1) {
    asm("mma.sync.aligned.m16n8k16.row.col.f32.f16.f16.f32 "
        "{%0,%1,%2,%3},{%4,%5,%6,%7},{%8,%9},{%0,%1,%2,%3};"
        : "+f"(acc[0]), "+f"(acc[1]), "+f"(acc[2]), "+f"(acc[3])
        : "r"(a[0]), "r"(a[1]), "r"(a[2]), "r"(a[3]), "r"(b0), "r"(b1));
}
__device__ __forceinline__ void ldsm4(uint32_t r[4], uint32_t saddr) {
    asm volatile("ldmatrix.sync.aligned.m8n8.x4.shared.b16 {%0,%1,%2,%3}, [%4];"
        : "=r"(r[0]), "=r"(r[1]), "=r"(r[2]), "=r"(r[3]) : "r"(saddr));
}
__device__ __forceinline__ float sigm(float x) {
    return __fdividef(1.f, 1.f + __expf(-x));
}
__device__ __forceinline__ float tanh_f(float x) {
    float ax = fabsf(x);
    float e  = __expf(-2.f * ax);
    float r  = __fdividef(1.f - e, 1.f + e);
    return copysignf(r, x);
}

// ------------------------------ prep kernels --------------------------------

// Pack weights into uint4-loadable fp16 B fragments, gate-blocked columns.
// half index: [l][gg][wn(8)][kt(32)][j(4)][lane(32)][h(8)]
// Column n_local = nt*8 + col (col = lane>>2), nt = 2j + (jj>>1):
//   gate = nt>>1, up = nt&1  ->  weight row r = gate*256 + gg*128 + wn*16 + up*8 + col
__global__ void prep_wfrag16(const float* __restrict__ Wih,
                             const float* __restrict__ Whh) {
    size_t idx = (size_t)blockIdx.x * 256 + threadIdx.x;
    int h    = (int)(idx & 7);
    int lane = (int)((idx >> 3)  & 31);
    int j    = (int)((idx >> 8)  & 3);
    int kt   = (int)((idx >> 10) & 31);
    int wn   = (int)((idx >> 15) & 7);
    int gg   = (int)((idx >> 18) & 1);
    int l    = (int)(idx >> 19);
    if (l >= LAYERS) return;
    int jj = h >> 1, hb = h & 1;
    int nt  = j * 2 + (jj >> 1);
    int col = lane >> 2;
    int k   = kt * 16 + (lane & 3) * 2 + hb + (jj & 1) * 8;
    int gate = nt >> 1, up = nt & 1;
    int r = gate * 256 + gg * 128 + wn * 16 + up * 8 + col;
    float v = (k < 256) ? Wih[((size_t)l * 1024 + r) * 256 + k]
                        : Whh[((size_t)l * 1024 + r) * 256 + (k - 256)];
    g_w16[idx] = __float2half(v);
}

// sbias[l][gg][wn*64 + nt*8 + cc] with the same gate-blocked mapping.
__global__ void prep_bias_init(const float* __restrict__ bih,
                               const float* __restrict__ bhh) {
    int idx = blockIdx.x * 256 + threadIdx.x;
    if (idx < LAYERS * 1024) {
        int l  = idx >> 10;
        int nl = idx & 1023;
        int gg = nl >> 9;
        int nn = nl & 511;
        int wn = nn >> 6;
        int nt = (nn >> 3) & 7;
        int cc = nn & 7;
        int gate = nt >> 1, up = nt & 1;
        int r = gate * 256 + gg * 128 + wn * 16 + up * 8 + cc;
        g_bias[idx] = bih[l * 1024 + r] + bhh[l * 1024 + r];
    }
    if (idx < 128) g_prog[idx] = 0;
}

__global__ void zero_h0() {
    uint4* p = (uint4*)(g_h16 + (size_t)blockIdx.x * HLAYER);  // slot 0
    for (int i = threadIdx.x; i < 2048; i += 256)
        p[i] = make_uint4(0u, 0u, 0u, 0u);
}

// --------------------------- persistent LSTM --------------------------------

__global__ void __launch_bounds__(256, 1)
lstm_persistent(const float* __restrict__ x) {
    extern __shared__ char smem[];
    __half* sA    = (__half*)smem;                                 // 64*520
    float*  sbias = (float*)(smem + 64 * SA_STRIDE * 2);

    const int l    = blockIdx.x >> 1;
    const int gg   = blockIdx.x & 1;
    const int tid  = threadIdx.x;
    const int lane = tid & 31;
    const int wn   = tid >> 5;      // 0..7 : 16-unit group
    const int q    = lane & 3;

    for (int i = tid; i < 512; i += 256)
        sbias[i] = g_bias[(l * GPL + gg) * 512 + i];
    __syncthreads();

    const uint4* wv = (const uint4*)(g_w16 +
        (size_t)((l * GPL + gg) * 8 + wn) * W_WARP_HALVES);
    __half* hlayer = g_h16 + (size_t)l * HLAYER;
    const __half* hprev = (l > 0) ? (g_h16 + (size_t)(l - 1) * HLAYER) : nullptr;

    uint32_t sA_base = (uint32_t)__cvta_generic_to_shared(sA);
    const int rowA = lane & 15;
    const int kofA = (lane >> 4) * 8;

    float acc[4][8][4];        // [mt][nt][frag]
    float creg[4][2][4];       // [mt][up][frag] : c-state, thread-resident
    #pragma unroll
    for (int mt = 0; mt < 4; ++mt)
        #pragma unroll
        for (int up = 0; up < 2; ++up)
            #pragma unroll
            for (int j = 0; j < 4; ++j) creg[mt][up][j] = 0.f;

    for (int t = 0; t < TSTEPS; ++t) {
        // ---- wait: peer >= t (h complete), prev layer >= t+1 (x ready) ----
        if (tid == 0) {
            if (t > 0) {
                while (ld_acq(&g_prog[l * GPL + (gg ^ 1)]) < (unsigned)t)
                    __nanosleep(32);
            }
            if (l > 0) {
                const unsigned need = (unsigned)(t + 1);
                for (;;) {
                    unsigned long long v = ld_acq64(&g_prog[(l - 1) * GPL]);
                    if ((unsigned)v >= need && (unsigned)(v >> 32) >= need) break;
                    __nanosleep(32);
                }
            }
        }
        __syncthreads();

        // ---- stage x_t -> sA[0,256), h_{t-1} -> sA[256,512) ----
        if (l == 0) {
            #pragma unroll
            for (int i = tid; i < 4096; i += 256) {       // 64 rows * 64 float4
                int row = i >> 6, c4 = i & 63;
                float4 v = __ldg((const float4*)(x +
                              ((size_t)row * TSTEPS + t) * 256) + c4);
                __half2* dst = (__half2*)(sA + row * SA_STRIDE + c4 * 4);
                dst[0] = __floats2half2_rn(v.x, v.y);
                dst[1] = __floats2half2_rn(v.z, v.w);
            }
        } else {
            const uint4* src = (const uint4*)(hprev + (size_t)(t + 1) * HSLOT);
            #pragma unroll
            for (int i = tid; i < 2048; i += 256) {       // 64 rows * 32 uint4
                int row = i >> 5, c8 = i & 31;
                *(uint4*)(sA + row * SA_STRIDE + c8 * 8) = __ldg(src + i);
            }
        }
        {
            const uint4* src = (const uint4*)(hlayer + (size_t)t * HSLOT);
            #pragma unroll
            for (int i = tid; i < 2048; i += 256) {
                int row = i >> 5, c8 = i & 31;
                *(uint4*)(sA + row * SA_STRIDE + 256 + c8 * 8) = __ldg(src + i);
            }
        }

        // ---- init accumulators with bias ----
        #pragma unroll
        for (int nt = 0; nt < 8; ++nt) {
            float b0 = sbias[wn * 64 + nt * 8 + q * 2];
            float b1 = sbias[wn * 64 + nt * 8 + q * 2 + 1];
            #pragma unroll
            for (int mt = 0; mt < 4; ++mt) {
                acc[mt][nt][0] = b0; acc[mt][nt][1] = b1;
                acc[mt][nt][2] = b0; acc[mt][nt][3] = b1;
            }
        }
        __syncthreads();

        // ---- GEMM: gates += [x_t | h_{t-1}] @ Wc^T (kt 0..15 x, 16..31 h) --
        {
            uint4 bb[4];
            #pragma unroll
            for (int jj = 0; jj < 4; ++jj)
                bb[jj] = __ldg(wv + jj * 32 + lane);
            #pragma unroll 4
            for (int kt = 0; kt < 32; ++kt) {
                uint4 nb[4];
                if (kt < 31) {
                    #pragma unroll
                    for (int jj = 0; jj < 4; ++jj)
                        nb[jj] = __ldg(wv + (kt + 1) * 128 + jj * 32 + lane);
                }
                uint32_t av[4][4];
                #pragma unroll
                for (int mt = 0; mt < 4; ++mt) {
                    uint32_t addr = sA_base + (uint32_t)(
                        ((mt * 16 + rowA) * SA_STRIDE + kt * 16 + kofA) * 2);
                    ldsm4(av[mt], addr);
                }
                #pragma unroll
                for (int jj = 0; jj < 4; ++jj) {
                    #pragma unroll
                    for (int mt = 0; mt < 4; ++mt) {
                        mma16(acc[mt][2 * jj],     av[mt], bb[jj].x, bb[jj].y);
                        mma16(acc[mt][2 * jj + 1], av[mt], bb[jj].z, bb[jj].w);
                    }
                }
                if (kt < 31) {
                    #pragma unroll
                    for (int jj = 0; jj < 4; ++jj) bb[jj] = nb[jj];
                }
            }
        }

        // ---- elementwise LSTM update (no shuffles, c in registers) ----
        // thread element (mt, up, j): row = mt*16 + (lane>>2) + (j>>1)*8,
        // unit = wn*16 + up*8 + 2q + (j&1); gates at nt = {up, 2+up, 4+up, 6+up}.
        __half* hout = hlayer + (size_t)(t + 1) * HSLOT + gg * 128;
        const int rbase = lane >> 2;
        const int ubase = wn * 16 + 2 * q;
        #pragma unroll
        for (int mt = 0; mt < 4; ++mt) {
            #pragma unroll
            for (int up = 0; up < 2; ++up) {
                float hv[4];
                #pragma unroll
                for (int j = 0; j < 4; ++j) {
                    float i_ = sigm(acc[mt][up][j]);
                    float f_ = sigm(acc[mt][2 + up][j]);
                    float g_ = tanh_f(acc[mt][4 + up][j]);
                    float o_ = sigm(acc[mt][6 + up][j]);
                    float cn = fmaf(f_, creg[mt][up][j], i_ * g_);
                    creg[mt][up][j] = cn;
                    hv[j] = o_ * tanh_f(cn);
                }
                int u    = ubase + up * 8;
                int row0 = mt * 16 + rbase;
                *(__half2*)(hout + (size_t)row0 * 256 + u) =
                    __floats2half2_rn(hv[0], hv[1]);
                *(__half2*)(hout + (size_t)(row0 + 8) * 256 + u) =
                    __floats2half2_rn(hv[2], hv[3]);
            }
        }

        __syncthreads();
        if (tid == 0) st_rel(&g_prog[l * GPL + gg], (unsigned)(t + 1));
    }
}

// ------------------------------ output head ---------------------------------

__global__ void out_proj(const float* __restrict__ Wout,
                         const float* __restrict__ bout,
                         float* __restrict__ out) {
    int p = blockIdx.x * 8 + (threadIdx.x >> 5);   // (t*64+b), 16384 total
    int lane = threadIdx.x & 31;
    int t = p >> 6, b = p & 63;
    const __half* h = g_h16 + (size_t)(LAYERS - 1) * HLAYER +
                      (size_t)(t + 1) * HSLOT + (size_t)b * 256 + lane * 8;
    uint4 hv = *(const uint4*)h;
    const __half2* hh = (const __half2*)&hv;
    const float* w0 = Wout + lane * 8;
    const float* w1 = Wout + 256 + lane * 8;
    float s0 = 0.f, s1 = 0.f;
    #pragma unroll
    for (int j = 0; j < 4; ++j) {
        float2 f = __half22float2(hh[j]);
        s0 += f.x * w0[2 * j] + f.y * w0[2 * j + 1];
        s1 += f.x * w1[2 * j] + f.y * w1[2 * j + 1];
    }
    #pragma unroll
    for (int off = 16; off > 0; off >>= 1) {
        s0 += __shfl_xor_sync(0xffffffffu, s0, off);
        s1 += __shfl_xor_sync(0xffffffffu, s1, off);
    }
    if (lane == 0) {
        out[(size_t)b * (TSTEPS * 2) + t * 2 + 0] = sigm(s0 + bout[0]);
        out[(size_t)b * (TSTEPS * 2) + t * 2 + 1] = sigm(s1 + bout[1]);
    }
}

// ------------------------------- launcher -----------------------------------

extern "C" void kernel_launch(void* const* d_in, const int* in_sizes, int n_in,
                              void* d_out, int out_size) {
    const float* x    = (const float*)d_in[0];
    const float* Wih  = (const float*)d_in[1];
    const float* Whh  = (const float*)d_in[2];
    const float* bih  = (const float*)d_in[3];
    const float* bhh  = (const float*)d_in[4];
    const float* Wout = (const float*)d_in[5];
    const float* bout = (const float*)d_in[6];
    float* out = (float*)d_out;

    cudaFuncSetAttribute(lstm_persistent,
                         cudaFuncAttributeMaxDynamicSharedMemorySize, SMEM_BYTES);

    prep_wfrag16<<<102400, 256>>>(Wih, Whh);    // 26.2M packed fp16 fragments
    prep_bias_init<<<200, 256>>>(bih, bhh);     // bias permute + progress reset
    zero_h0<<<LAYERS, 256>>>();                 // h_{-1} = 0 slots (fp16)
    lstm_persistent<<<NCTA, 256, SMEM_BYTES>>>(x);
    out_proj<<<2048, 256>>>(Wout, bout, out);   // final sigmoid head
}

// round 9
// speedup vs baseline: 3.8249x; 1.0356x over previous
#include <cuda_runtime.h>
#include <cuda_fp16.h>
#include <cstdint>
#include <cstddef>

// ---------------------------------------------------------------------------
// 50-layer LSTM, persistent wavefront, fp16 m16n8k16 mma.sync.
//   B=64, T=256, D=H=256, L=50, O=2
//   R9: depth-2 B prefetch (c-state moved to SMEM to free regs),
//       MUFU.TANH-based activations (5 MUFU/elem vs 10),
//       own-h written directly to SMEM (only peer half staged from global).
//   Warp wn owns units [16wn,16wn+16); its 64 cols = [i|f|g|o] x 16 units.
// ---------------------------------------------------------------------------

#define LAYERS 50
#define TSTEPS 256
#define GPL    2
#define NCTA   (LAYERS*GPL)                // 100 persistent CTAs, all resident
#define HSLOT  16384                       // 64*256 halves per time slot
#define HLAYER ((size_t)(TSTEPS+1)*HSLOT)

#define SA_STRIDE 520                      // halves per SMEM A row
#define CB_STRIDE 136                      // floats per cbuf row
#define W_WARP_HALVES 32768                // per (l,gg,wn): 32kt*4j*32lane*8h
#define SMEM_BYTES (64*SA_STRIDE*2 + 64*CB_STRIDE*4 + 512*4)   // 103424

__device__ __half   g_h16[(size_t)LAYERS*HLAYER];                 // ~421 MB
__device__ __half   g_w16[(size_t)LAYERS*2*8*W_WARP_HALVES];      // ~52 MB
__device__ float    g_bias[LAYERS*1024];
__device__ unsigned g_prog[128];

// ------------------------------- helpers -----------------------------------

__device__ __forceinline__ unsigned ld_acq(const unsigned* p) {
    unsigned v;
    asm volatile("ld.acquire.gpu.u32 %0, [%1];" : "=r"(v) : "l"(p) : "memory");
    return v;
}
__device__ __forceinline__ unsigned long long ld_acq64(const unsigned* p) {
    unsigned long long v;
    asm volatile("ld.acquire.gpu.u64 %0, [%1];" : "=l"(v) : "l"(p) : "memory");
    return v;
}
__device__ __forceinline__ void st_rel(unsigned* p, unsigned v) {
    asm volatile("st.release.gpu.u32 [%0], %1;" :: "l"(p), "r"(v) : "memory");
}
__device__ __forceinline__ void mma16(float* acc, const uint32_t a[4],
                                      uint32_t b0, uint32_t b1) {
    asm("mma.sync.aligned.m16n8k16.row.col.f32.f16.f16.f32 "
        "{%0,%1,%2,%3},{%4,%5,%6,%7},{%8,%9},{%0,%1,%2,%3};"
        : "+f"(acc[0]), "+f"(acc[1]), "+f"(acc[2]), "+f"(acc[3])
        : "r"(a[0]), "r"(a[1]), "r"(a[2]), "r"(a[3]), "r"(b0), "r"(b1));
}
__device__ __forceinline__ void ldsm4(uint32_t r[4], uint32_t saddr) {
    asm volatile("ldmatrix.sync.aligned.m8n8.x4.shared.b16 {%0,%1,%2,%3}, [%4];"
        : "=r"(r[0]), "=r"(r[1]), "=r"(r[2]), "=r"(r[3]) : "r"(saddr));
}
__device__ __forceinline__ float tanhfast(float x) {
    float y;
    asm("tanh.approx.f32 %0, %1;" : "=f"(y) : "f"(x));
    return y;
}
__device__ __forceinline__ float sigm(float x) {          // 1 MUFU
    return fmaf(tanhfast(0.5f * x), 0.5f, 0.5f);
}

// ------------------------------ prep kernels --------------------------------

// Pack weights into uint4-loadable fp16 B fragments, gate-blocked columns.
// half index: [l][gg][wn(8)][kt(32)][j(4)][lane(32)][h(8)]
__global__ void prep_wfrag16(const float* __restrict__ Wih,
                             const float* __restrict__ Whh) {
    size_t idx = (size_t)blockIdx.x * 256 + threadIdx.x;
    int h    = (int)(idx & 7);
    int lane = (int)((idx >> 3)  & 31);
    int j    = (int)((idx >> 8)  & 3);
    int kt   = (int)((idx >> 10) & 31);
    int wn   = (int)((idx >> 15) & 7);
    int gg   = (int)((idx >> 18) & 1);
    int l    = (int)(idx >> 19);
    if (l >= LAYERS) return;
    int jj = h >> 1, hb = h & 1;
    int nt  = j * 2 + (jj >> 1);
    int col = lane >> 2;
    int k   = kt * 16 + (lane & 3) * 2 + hb + (jj & 1) * 8;
    int gate = nt >> 1, up = nt & 1;
    int r = gate * 256 + gg * 128 + wn * 16 + up * 8 + col;
    float v = (k < 256) ? Wih[((size_t)l * 1024 + r) * 256 + k]
                        : Whh[((size_t)l * 1024 + r) * 256 + (k - 256)];
    g_w16[idx] = __float2half(v);
}

__global__ void prep_bias_init(const float* __restrict__ bih,
                               const float* __restrict__ bhh) {
    int idx = blockIdx.x * 256 + threadIdx.x;
    if (idx < LAYERS * 1024) {
        int l  = idx >> 10;
        int nl = idx & 1023;
        int gg = nl >> 9;
        int nn = nl & 511;
        int wn = nn >> 6;
        int nt = (nn >> 3) & 7;
        int cc = nn & 7;
        int gate = nt >> 1, up = nt & 1;
        int r = gate * 256 + gg * 128 + wn * 16 + up * 8 + cc;
        g_bias[idx] = bih[l * 1024 + r] + bhh[l * 1024 + r];
    }
    if (idx < 128) g_prog[idx] = 0;
}

__global__ void zero_h0() {
    uint4* p = (uint4*)(g_h16 + (size_t)blockIdx.x * HLAYER);  // slot 0
    for (int i = threadIdx.x; i < 2048; i += 256)
        p[i] = make_uint4(0u, 0u, 0u, 0u);
}

// --------------------------- persistent LSTM --------------------------------

#define MMA_BLOCK(BUF)                                                        \
    _Pragma("unroll")                                                         \
    for (int jj = 0; jj < 4; ++jj) {                                          \
        _Pragma("unroll")                                                     \
        for (int mt = 0; mt < 4; ++mt) {                                      \
            mma16(acc[mt][2 * jj],     av[mt], BUF[jj].x, BUF[jj].y);         \
            mma16(acc[mt][2 * jj + 1], av[mt], BUF[jj].z, BUF[jj].w);         \
        }                                                                     \
    }

__global__ void __launch_bounds__(256, 1)
lstm_persistent(const float* __restrict__ x) {
    extern __shared__ char smem[];
    __half* sA    = (__half*)smem;                                 // 64*520
    float*  cbuf  = (float*)(smem + 64 * SA_STRIDE * 2);           // 64*136
    float*  sbias = (float*)(smem + 64 * SA_STRIDE * 2 + 64 * CB_STRIDE * 4);

    const int l    = blockIdx.x >> 1;
    const int gg   = blockIdx.x & 1;
    const int tid  = threadIdx.x;
    const int lane = tid & 31;
    const int wn   = tid >> 5;      // 0..7 : 16-unit group
    const int q    = lane & 3;

    for (int i = tid; i < 512; i += 256)
        sbias[i] = g_bias[(l * GPL + gg) * 512 + i];
    for (int i = tid; i < 64 * CB_STRIDE; i += 256) cbuf[i] = 0.f;
    // zero own h half in sA (h_{-1} = 0); peer half comes from global slot 0
    for (int i = tid; i < 1024; i += 256) {
        int row = i >> 4, c8 = i & 15;
        *(uint4*)(sA + row * SA_STRIDE + 256 + gg * 128 + c8 * 8) =
            make_uint4(0u, 0u, 0u, 0u);
    }
    __syncthreads();

    const uint4* wv = (const uint4*)(g_w16 +
        (size_t)((l * GPL + gg) * 8 + wn) * W_WARP_HALVES);
    __half* hlayer = g_h16 + (size_t)l * HLAYER;
    const __half* hprev = (l > 0) ? (g_h16 + (size_t)(l - 1) * HLAYER) : nullptr;

    uint32_t sA_base = (uint32_t)__cvta_generic_to_shared(sA);
    const int rowA = lane & 15;
    const int kofA = (lane >> 4) * 8;
    const int peer = gg ^ 1;

    float acc[4][8][4];        // [mt][nt][frag]

    for (int t = 0; t < TSTEPS; ++t) {
        // ---- wait: peer >= t (peer h half), prev layer >= t+1 (x ready) ----
        if (tid == 0) {
            if (t > 0) {
                while (ld_acq(&g_prog[l * GPL + peer]) < (unsigned)t)
                    __nanosleep(32);
            }
            if (l > 0) {
                const unsigned need = (unsigned)(t + 1);
                for (;;) {
                    unsigned long long v = ld_acq64(&g_prog[(l - 1) * GPL]);
                    if ((unsigned)v >= need && (unsigned)(v >> 32) >= need) break;
                    __nanosleep(32);
                }
            }
        }
        __syncthreads();

        // ---- stage x_t -> sA[0,256), peer h half -> sA[256+peer*128, +128) --
        if (l == 0) {
            #pragma unroll
            for (int i = tid; i < 4096; i += 256) {       // 64 rows * 64 float4
                int row = i >> 6, c4 = i & 63;
                float4 v = __ldg((const float4*)(x +
                              ((size_t)row * TSTEPS + t) * 256) + c4);
                __half2* dst = (__half2*)(sA + row * SA_STRIDE + c4 * 4);
                dst[0] = __floats2half2_rn(v.x, v.y);
                dst[1] = __floats2half2_rn(v.z, v.w);
            }
        } else {
            const uint4* src = (const uint4*)(hprev + (size_t)(t + 1) * HSLOT);
            #pragma unroll
            for (int i = tid; i < 2048; i += 256) {       // 64 rows * 32 uint4
                int row = i >> 5, c8 = i & 31;
                *(uint4*)(sA + row * SA_STRIDE + c8 * 8) = __ldg(src + i);
            }
        }
        {
            const __half* srcp = hlayer + (size_t)t * HSLOT + peer * 128;
            #pragma unroll
            for (int i = tid; i < 1024; i += 256) {       // 64 rows * 16 uint4
                int row = i >> 4, c8 = i & 15;
                *(uint4*)(sA + row * SA_STRIDE + 256 + peer * 128 + c8 * 8) =
                    __ldg((const uint4*)(srcp + (size_t)row * 256) + c8);
            }
        }

        // ---- init accumulators with bias ----
        #pragma unroll
        for (int nt = 0; nt < 8; ++nt) {
            float b0 = sbias[wn * 64 + nt * 8 + q * 2];
            float b1 = sbias[wn * 64 + nt * 8 + q * 2 + 1];
            #pragma unroll
            for (int mt = 0; mt < 4; ++mt) {
                acc[mt][nt][0] = b0; acc[mt][nt][1] = b1;
                acc[mt][nt][2] = b0; acc[mt][nt][3] = b1;
            }
        }
        __syncthreads();

        // ---- GEMM: gates += [x_t | h_{t-1}] @ Wc^T, depth-2 B prefetch ----
        {
            uint4 buf0[4], buf1[4];
            #pragma unroll
            for (int jj = 0; jj < 4; ++jj) {
                buf0[jj] = __ldg(wv + jj * 32 + lane);
                buf1[jj] = __ldg(wv + 128 + jj * 32 + lane);
            }
            #pragma unroll 4
            for (int kt = 0; kt < 32; ++kt) {
                uint32_t av[4][4];
                #pragma unroll
                for (int mt = 0; mt < 4; ++mt) {
                    uint32_t addr = sA_base + (uint32_t)(
                        ((mt * 16 + rowA) * SA_STRIDE + kt * 16 + kofA) * 2);
                    ldsm4(av[mt], addr);
                }
                uint4 nb[4];
                if (kt < 30) {
                    #pragma unroll
                    for (int jj = 0; jj < 4; ++jj)
                        nb[jj] = __ldg(wv + (kt + 2) * 128 + jj * 32 + lane);
                }
                if (kt & 1) {
                    MMA_BLOCK(buf1)
                    if (kt < 30) {
                        #pragma unroll
                        for (int jj = 0; jj < 4; ++jj) buf1[jj] = nb[jj];
                    }
                } else {
                    MMA_BLOCK(buf0)
                    if (kt < 30) {
                        #pragma unroll
                        for (int jj = 0; jj < 4; ++jj) buf0[jj] = nb[jj];
                    }
                }
            }
        }
        __syncthreads();   // all LDSM done before sA h-region is rewritten

        // ---- elementwise LSTM update (tanh.approx, c in SMEM) ----
        // element (mt,up,j): row = mt*16 + (lane>>2) + (j>>1)*8,
        // local unit ul = wn*16 + up*8 + 2q + (j&1); gates nt = {up,2+up,4+up,6+up}
        __half* houtg = hlayer + (size_t)(t + 1) * HSLOT + gg * 128;
        __half* houts = sA + 256 + gg * 128;
        const int rbase = lane >> 2;
        const int ulb = wn * 16 + 2 * q;
        #pragma unroll
        for (int mt = 0; mt < 4; ++mt) {
            #pragma unroll
            for (int up = 0; up < 2; ++up) {
                int ul   = ulb + up * 8;
                int row0 = mt * 16 + rbase;
                float2 c01 = *(float2*)&cbuf[row0 * CB_STRIDE + ul];
                float2 c23 = *(float2*)&cbuf[(row0 + 8) * CB_STRIDE + ul];
                float cv[4] = {c01.x, c01.y, c23.x, c23.y};
                float hv[4];
                #pragma unroll
                for (int j = 0; j < 4; ++j) {
                    float i_ = sigm(acc[mt][up][j]);
                    float f_ = sigm(acc[mt][2 + up][j]);
                    float g_ = tanhfast(acc[mt][4 + up][j]);
                    float o_ = sigm(acc[mt][6 + up][j]);
                    float cn = fmaf(f_, cv[j], i_ * g_);
                    cv[j] = cn;
                    hv[j] = o_ * tanhfast(cn);
                }
                *(float2*)&cbuf[row0 * CB_STRIDE + ul]       = make_float2(cv[0], cv[1]);
                *(float2*)&cbuf[(row0 + 8) * CB_STRIDE + ul] = make_float2(cv[2], cv[3]);
                __half2 h01 = __floats2half2_rn(hv[0], hv[1]);
                __half2 h23 = __floats2half2_rn(hv[2], hv[3]);
                *(__half2*)(houtg + (size_t)row0 * 256 + ul)       = h01;
                *(__half2*)(houtg + (size_t)(row0 + 8) * 256 + ul) = h23;
                *(__half2*)(houts + row0 * SA_STRIDE + ul)         = h01;
                *(__half2*)(houts + (row0 + 8) * SA_STRIDE + ul)   = h23;
            }
        }

        __syncthreads();
        if (tid == 0) st_rel(&g_prog[l * GPL + gg], (unsigned)(t + 1));
    }
}

// ------------------------------ output head ---------------------------------

__global__ void out_proj(const float* __restrict__ Wout,
                         const float* __restrict__ bout,
                         float* __restrict__ out) {
    int p = blockIdx.x * 8 + (threadIdx.x >> 5);   // (t*64+b), 16384 total
    int lane = threadIdx.x & 31;
    int t = p >> 6, b = p & 63;
    const __half* h = g_h16 + (size_t)(LAYERS - 1) * HLAYER +
                      (size_t)(t + 1) * HSLOT + (size_t)b * 256 + lane * 8;
    uint4 hv = *(const uint4*)h;
    const __half2* hh = (const __half2*)&hv;
    const float* w0 = Wout + lane * 8;
    const float* w1 = Wout + 256 + lane * 8;
    float s0 = 0.f, s1 = 0.f;
    #pragma unroll
    for (int j = 0; j < 4; ++j) {
        float2 f = __half22float2(hh[j]);
        s0 += f.x * w0[2 * j] + f.y * w0[2 * j + 1];
        s1 += f.x * w1[2 * j] + f.y * w1[2 * j + 1];
    }
    #pragma unroll
    for (int off = 16; off > 0; off >>= 1) {
        s0 += __shfl_xor_sync(0xffffffffu, s0, off);
        s1 += __shfl_xor_sync(0xffffffffu, s1, off);
    }
    if (lane == 0) {
        float e0 = __expf(-(s0 + bout[0]));
        float e1 = __expf(-(s1 + bout[1]));
        out[(size_t)b * (TSTEPS * 2) + t * 2 + 0] = __fdividef(1.f, 1.f + e0);
        out[(size_t)b * (TSTEPS * 2) + t * 2 + 1] = __fdividef(1.f, 1.f + e1);
    }
}

// ------------------------------- launcher -----------------------------------

extern "C" void kernel_launch(void* const* d_in, const int* in_sizes, int n_in,
                              void* d_out, int out_size) {
    const float* x    = (const float*)d_in[0];
    const float* Wih  = (const float*)d_in[1];
    const float* Whh  = (const float*)d_in[2];
    const float* bih  = (const float*)d_in[3];
    const float* bhh  = (const float*)d_in[4];
    const float* Wout = (const float*)d_in[5];
    const float* bout = (const float*)d_in[6];
    float* out = (float*)d_out;

    cudaFuncSetAttribute(lstm_persistent,
                         cudaFuncAttributeMaxDynamicSharedMemorySize, SMEM_BYTES);

    prep_wfrag16<<<102400, 256>>>(Wih, Whh);    // 26.2M packed fp16 fragments
    prep_bias_init<<<200, 256>>>(bih, bhh);     // bias permute + progress reset
    zero_h0<<<LAYERS, 256>>>();                 // h_{-1} = 0 slots (fp16)
    lstm_persistent<<<NCTA, 256, SMEM_BYTES>>>(x);
    out_proj<<<2048, 256>>>(Wout, bout, out);   // final sigmoid head
}

// round 10
// speedup vs baseline: 4.0441x; 1.0573x over previous
#include <cuda_runtime.h>
#include <cuda_fp16.h>
#include <cstdint>
#include <cstddef>

// ---------------------------------------------------------------------------
// 50-layer LSTM, persistent wavefront, fp16 m16n8k16 mma.sync.
//   B=64, T=256, D=H=256, L=50, O=2
//   R10: 512 threads / 16 warps, warp tile 64x32 (warp owns 8 units x 4 gates)
//        -> 4 warps/SMSP for latency hiding, ~1200 instr/warp/step,
//        acc 64 regs, B loaded once per CTA, c-state in SMEM.
// ---------------------------------------------------------------------------

#define LAYERS 50
#define TSTEPS 256
#define GPL    2
#define NCTA   (LAYERS*GPL)                // 100 persistent CTAs, all resident
#define HSLOT  16384                       // 64*256 halves per time slot
#define HLAYER ((size_t)(TSTEPS+1)*HSLOT)

#define SA_STRIDE 520                      // halves per SMEM A row
#define CB_STRIDE 136                      // floats per cbuf row
#define W_WARP_HALVES 16384                // per (l,gg,wn): 32kt*2j*32lane*8h
#define SMEM_BYTES (64*SA_STRIDE*2 + 64*CB_STRIDE*4 + 512*4)   // 103424

__device__ __half   g_h16[(size_t)LAYERS*HLAYER];                 // ~421 MB
__device__ __half   g_w16[(size_t)LAYERS*2*16*W_WARP_HALVES];     // ~52 MB
__device__ float    g_bias[LAYERS*1024];
__device__ unsigned g_prog[128];

// ------------------------------- helpers -----------------------------------

__device__ __forceinline__ unsigned ld_acq(const unsigned* p) {
    unsigned v;
    asm volatile("ld.acquire.gpu.u32 %0, [%1];" : "=r"(v) : "l"(p) : "memory");
    return v;
}
__device__ __forceinline__ unsigned long long ld_acq64(const unsigned* p) {
    unsigned long long v;
    asm volatile("ld.acquire.gpu.u64 %0, [%1];" : "=l"(v) : "l"(p) : "memory");
    return v;
}
__device__ __forceinline__ void st_rel(unsigned* p, unsigned v) {
    asm volatile("st.release.gpu.u32 [%0], %1;" :: "l"(p), "r"(v) : "memory");
}
__device__ __forceinline__ void mma16(float* acc, const uint32_t a[4],
                                      uint32_t b0, uint32_t b1) {
    asm("mma.sync.aligned.m16n8k16.row.col.f32.f16.f16.f32 "
        "{%0,%1,%2,%3},{%4,%5,%6,%7},{%8,%9},{%0,%1,%2,%3};"
        : "+f"(acc[0]), "+f"(acc[1]), "+f"(acc[2]), "+f"(acc[3])
        : "r"(a[0]), "r"(a[1]), "r"(a[2]), "r"(a[3]), "r"(b0), "r"(b1));
}
__device__ __forceinline__ void ldsm4(uint32_t r[4], uint32_t saddr) {
    asm volatile("ldmatrix.sync.aligned.m8n8.x4.shared.b16 {%0,%1,%2,%3}, [%4];"
        : "=r"(r[0]), "=r"(r[1]), "=r"(r[2]), "=r"(r[3]) : "r"(saddr));
}
__device__ __forceinline__ float tanhfast(float x) {
    float y;
    asm("tanh.approx.f32 %0, %1;" : "=f"(y) : "f"(x));
    return y;
}
__device__ __forceinline__ float sigm(float x) {          // 1 MUFU
    return fmaf(tanhfast(0.5f * x), 0.5f, 0.5f);
}

// ------------------------------ prep kernels --------------------------------

// Pack weights into uint4-loadable fp16 B fragments, gate-blocked columns.
// half index: [l][gg][wn(16)][kt(32)][j(2)][lane(32)][h(8)]
// Warp wn owns units [8wn, 8wn+8); its 32 cols = gate(nt) x 8 units.
__global__ void prep_wfrag16(const float* __restrict__ Wih,
                             const float* __restrict__ Whh) {
    size_t idx = (size_t)blockIdx.x * 256 + threadIdx.x;
    int h    = (int)(idx & 7);
    int lane = (int)((idx >> 3)  & 31);
    int j    = (int)((idx >> 8)  & 1);
    int kt   = (int)((idx >> 9)  & 31);
    int wn   = (int)((idx >> 14) & 15);
    int gg   = (int)((idx >> 18) & 1);
    int l    = (int)(idx >> 19);
    if (l >= LAYERS) return;
    int jj = h >> 1, hb = h & 1;
    int nt  = j * 2 + (jj >> 1);             // gate 0..3 (i,f,g,o)
    int col = lane >> 2;                     // unit offset 0..7
    int k   = kt * 16 + (lane & 3) * 2 + hb + (jj & 1) * 8;
    int r = nt * 256 + gg * 128 + wn * 8 + col;
    float v = (k < 256) ? Wih[((size_t)l * 1024 + r) * 256 + k]
                        : Whh[((size_t)l * 1024 + r) * 256 + (k - 256)];
    g_w16[idx] = __float2half(v);
}

// sbias[l][gg][wn*32 + nt*8 + cc]
__global__ void prep_bias_init(const float* __restrict__ bih,
                               const float* __restrict__ bhh) {
    int idx = blockIdx.x * 256 + threadIdx.x;
    if (idx < LAYERS * 1024) {
        int l  = idx >> 10;
        int nl = idx & 1023;
        int gg = nl >> 9;
        int nn = nl & 511;
        int wn = nn >> 5;
        int nt = (nn >> 3) & 3;
        int cc = nn & 7;
        int r = nt * 256 + gg * 128 + wn * 8 + cc;
        g_bias[idx] = bih[l * 1024 + r] + bhh[l * 1024 + r];
    }
    if (idx < 128) g_prog[idx] = 0;
}

__global__ void zero_h0() {
    uint4* p = (uint4*)(g_h16 + (size_t)blockIdx.x * HLAYER);  // slot 0
    for (int i = threadIdx.x; i < 2048; i += 256)
        p[i] = make_uint4(0u, 0u, 0u, 0u);
}

// --------------------------- persistent LSTM --------------------------------

#define MMA_BLOCK(B0, B1)                                                     \
    _Pragma("unroll")                                                         \
    for (int mt = 0; mt < 4; ++mt) {                                          \
        mma16(acc[mt][0], av[mt], (B0).x, (B0).y);                            \
        mma16(acc[mt][1], av[mt], (B0).z, (B0).w);                            \
        mma16(acc[mt][2], av[mt], (B1).x, (B1).y);                            \
        mma16(acc[mt][3], av[mt], (B1).z, (B1).w);                            \
    }

__global__ void __launch_bounds__(512, 1)
lstm_persistent(const float* __restrict__ x) {
    extern __shared__ char smem[];
    __half* sA    = (__half*)smem;                                 // 64*520
    float*  cbuf  = (float*)(smem + 64 * SA_STRIDE * 2);           // 64*136
    float*  sbias = (float*)(smem + 64 * SA_STRIDE * 2 + 64 * CB_STRIDE * 4);

    const int l    = blockIdx.x >> 1;
    const int gg   = blockIdx.x & 1;
    const int tid  = threadIdx.x;
    const int lane = tid & 31;
    const int wn   = tid >> 5;      // 0..15 : 8-unit group
    const int q    = lane & 3;

    if (tid < 512) sbias[tid] = g_bias[(l * GPL + gg) * 512 + tid];
    for (int i = tid; i < 64 * CB_STRIDE; i += 512) cbuf[i] = 0.f;
    // zero own h half in sA (h_{-1} = 0); peer half comes from global slot 0
    for (int i = tid; i < 1024; i += 512) {
        int row = i >> 4, c8 = i & 15;
        *(uint4*)(sA + row * SA_STRIDE + 256 + gg * 128 + c8 * 8) =
            make_uint4(0u, 0u, 0u, 0u);
    }
    __syncthreads();

    const uint4* wv = (const uint4*)(g_w16 +
        (size_t)((l * GPL + gg) * 16 + wn) * W_WARP_HALVES);
    __half* hlayer = g_h16 + (size_t)l * HLAYER;
    const __half* hprev = (l > 0) ? (g_h16 + (size_t)(l - 1) * HLAYER) : nullptr;

    uint32_t sA_base = (uint32_t)__cvta_generic_to_shared(sA);
    const int rowA = lane & 15;
    const int kofA = (lane >> 4) * 8;
    const int peer = gg ^ 1;

    float acc[4][4][4];        // [mt][gate][frag] : 64 regs

    for (int t = 0; t < TSTEPS; ++t) {
        // ---- wait: peer >= t (peer h half), prev layer >= t+1 (x ready) ----
        if (tid == 0) {
            if (t > 0) {
                while (ld_acq(&g_prog[l * GPL + peer]) < (unsigned)t)
                    __nanosleep(32);
            }
            if (l > 0) {
                const unsigned need = (unsigned)(t + 1);
                for (;;) {
                    unsigned long long v = ld_acq64(&g_prog[(l - 1) * GPL]);
                    if ((unsigned)v >= need && (unsigned)(v >> 32) >= need) break;
                    __nanosleep(32);
                }
            }
        }
        __syncthreads();

        // ---- stage x_t -> sA[0,256), peer h half -> sA[256+peer*128,+128) --
        if (l == 0) {
            #pragma unroll
            for (int i = tid; i < 4096; i += 512) {       // 64 rows * 64 float4
                int row = i >> 6, c4 = i & 63;
                float4 v = __ldg((const float4*)(x +
                              ((size_t)row * TSTEPS + t) * 256) + c4);
                __half2* dst = (__half2*)(sA + row * SA_STRIDE + c4 * 4);
                dst[0] = __floats2half2_rn(v.x, v.y);
                dst[1] = __floats2half2_rn(v.z, v.w);
            }
        } else {
            const uint4* src = (const uint4*)(hprev + (size_t)(t + 1) * HSLOT);
            #pragma unroll
            for (int i = tid; i < 2048; i += 512) {       // 64 rows * 32 uint4
                int row = i >> 5, c8 = i & 31;
                *(uint4*)(sA + row * SA_STRIDE + c8 * 8) = __ldg(src + i);
            }
        }
        {
            const __half* srcp = hlayer + (size_t)t * HSLOT + peer * 128;
            #pragma unroll
            for (int i = tid; i < 1024; i += 512) {       // 64 rows * 16 uint4
                int row = i >> 4, c8 = i & 15;
                *(uint4*)(sA + row * SA_STRIDE + 256 + peer * 128 + c8 * 8) =
                    __ldg((const uint4*)(srcp + (size_t)row * 256) + c8);
            }
        }

        // ---- init accumulators with bias ----
        #pragma unroll
        for (int nt = 0; nt < 4; ++nt) {
            float b0 = sbias[wn * 32 + nt * 8 + q * 2];
            float b1 = sbias[wn * 32 + nt * 8 + q * 2 + 1];
            #pragma unroll
            for (int mt = 0; mt < 4; ++mt) {
                acc[mt][nt][0] = b0; acc[mt][nt][1] = b1;
                acc[mt][nt][2] = b0; acc[mt][nt][3] = b1;
            }
        }
        __syncthreads();

        // ---- GEMM: gates += [x_t | h_{t-1}] @ Wc^T, depth-2 B prefetch ----
        {
            uint4 b0a = __ldg(wv + lane);
            uint4 b0b = __ldg(wv + 32 + lane);
            uint4 b1a = __ldg(wv + 64 + lane);
            uint4 b1b = __ldg(wv + 96 + lane);
            #pragma unroll 4
            for (int kt = 0; kt < 32; ++kt) {
                uint32_t av[4][4];
                #pragma unroll
                for (int mt = 0; mt < 4; ++mt) {
                    uint32_t addr = sA_base + (uint32_t)(
                        ((mt * 16 + rowA) * SA_STRIDE + kt * 16 + kofA) * 2);
                    ldsm4(av[mt], addr);
                }
                uint4 na, nb;
                if (kt < 30) {
                    na = __ldg(wv + (kt + 2) * 64 + lane);
                    nb = __ldg(wv + (kt + 2) * 64 + 32 + lane);
                }
                if (kt & 1) {
                    MMA_BLOCK(b1a, b1b)
                    if (kt < 30) { b1a = na; b1b = nb; }
                } else {
                    MMA_BLOCK(b0a, b0b)
                    if (kt < 30) { b0a = na; b0b = nb; }
                }
            }
        }
        __syncthreads();   // all LDSM done before sA h-region is rewritten

        // ---- elementwise LSTM update (tanh.approx, c in SMEM) ----
        // element (mt,j): row = mt*16 + (lane>>2) + (j>>1)*8,
        // unit u = wn*8 + 2q + (j&1); gates acc[mt][0..3][j] = i,f,g,o
        __half* houtg = hlayer + (size_t)(t + 1) * HSLOT + gg * 128;
        __half* houts = sA + 256 + gg * 128;
        const int rbase = lane >> 2;
        const int u0 = wn * 8 + 2 * q;
        #pragma unroll
        for (int mt = 0; mt < 4; ++mt) {
            int row0 = mt * 16 + rbase;
            float2 c01 = *(float2*)&cbuf[row0 * CB_STRIDE + u0];
            float2 c23 = *(float2*)&cbuf[(row0 + 8) * CB_STRIDE + u0];
            float cv[4] = {c01.x, c01.y, c23.x, c23.y};
            float hv[4];
            #pragma unroll
            for (int j = 0; j < 4; ++j) {
                float i_ = sigm(acc[mt][0][j]);
                float f_ = sigm(acc[mt][1][j]);
                float g_ = tanhfast(acc[mt][2][j]);
                float o_ = sigm(acc[mt][3][j]);
                float cn = fmaf(f_, cv[j], i_ * g_);
                cv[j] = cn;
                hv[j] = o_ * tanhfast(cn);
            }
            *(float2*)&cbuf[row0 * CB_STRIDE + u0]       = make_float2(cv[0], cv[1]);
            *(float2*)&cbuf[(row0 + 8) * CB_STRIDE + u0] = make_float2(cv[2], cv[3]);
            __half2 h01 = __floats2half2_rn(hv[0], hv[1]);
            __half2 h23 = __floats2half2_rn(hv[2], hv[3]);
            *(__half2*)(houtg + (size_t)row0 * 256 + u0)       = h01;
            *(__half2*)(houtg + (size_t)(row0 + 8) * 256 + u0) = h23;
            *(__half2*)(houts + row0 * SA_STRIDE + u0)         = h01;
            *(__half2*)(houts + (row0 + 8) * SA_STRIDE + u0)   = h23;
        }

        __syncthreads();
        if (tid == 0) st_rel(&g_prog[l * GPL + gg], (unsigned)(t + 1));
    }
}

// ------------------------------ output head ---------------------------------

__global__ void out_proj(const float* __restrict__ Wout,
                         const float* __restrict__ bout,
                         float* __restrict__ out) {
    int p = blockIdx.x * 8 + (threadIdx.x >> 5);   // (t*64+b), 16384 total
    int lane = threadIdx.x & 31;
    int t = p >> 6, b = p & 63;
    const __half* h = g_h16 + (size_t)(LAYERS - 1) * HLAYER +
                      (size_t)(t + 1) * HSLOT + (size_t)b * 256 + lane * 8;
    uint4 hv = *(const uint4*)h;
    const __half2* hh = (const __half2*)&hv;
    const float* w0 = Wout + lane * 8;
    const float* w1 = Wout + 256 + lane * 8;
    float s0 = 0.f, s1 = 0.f;
    #pragma unroll
    for (int j = 0; j < 4; ++j) {
        float2 f = __half22float2(hh[j]);
        s0 += f.x * w0[2 * j] + f.y * w0[2 * j + 1];
        s1 += f.x * w1[2 * j] + f.y * w1[2 * j + 1];
    }
    #pragma unroll
    for (int off = 16; off > 0; off >>= 1) {
        s0 += __shfl_xor_sync(0xffffffffu, s0, off);
        s1 += __shfl_xor_sync(0xffffffffu, s1, off);
    }
    if (lane == 0) {
        float e0 = __expf(-(s0 + bout[0]));
        float e1 = __expf(-(s1 + bout[1]));
        out[(size_t)b * (TSTEPS * 2) + t * 2 + 0] = __fdividef(1.f, 1.f + e0);
        out[(size_t)b * (TSTEPS * 2) + t * 2 + 1] = __fdividef(1.f, 1.f + e1);
    }
}

// ------------------------------- launcher -----------------------------------

extern "C" void kernel_launch(void* const* d_in, const int* in_sizes, int n_in,
                              void* d_out, int out_size) {
    const float* x    = (const float*)d_in[0];
    const float* Wih  = (const float*)d_in[1];
    const float* Whh  = (const float*)d_in[2];
    const float* bih  = (const float*)d_in[3];
    const float* bhh  = (const float*)d_in[4];
    const float* Wout = (const float*)d_in[5];
    const float* bout = (const float*)d_in[6];
    float* out = (float*)d_out;

    cudaFuncSetAttribute(lstm_persistent,
                         cudaFuncAttributeMaxDynamicSharedMemorySize, SMEM_BYTES);

    prep_wfrag16<<<102400, 256>>>(Wih, Whh);    // 26.2M packed fp16 fragments
    prep_bias_init<<<200, 256>>>(bih, bhh);     // bias permute + progress reset
    zero_h0<<<LAYERS, 256>>>();                 // h_{-1} = 0 slots (fp16)
    lstm_persistent<<<NCTA, 512, SMEM_BYTES>>>(x);
    out_proj<<<2048, 256>>>(Wout, bout, out);   // final sigmoid head
}

// round 11
// speedup vs baseline: 4.2039x; 1.0395x over previous
#include <cuda_runtime.h>
#include <cuda_fp16.h>
#include <cstdint>
#include <cstddef>

// ---------------------------------------------------------------------------
// 50-layer LSTM, persistent wavefront, fp16 m16n8k16 mma.sync.
//   B=64, T=256, D=H=256, L=50, O=2
//   R11: GPL=4 -> 200 CTAs, 2 co-resident CTAs per SM (different layers).
//        Cross-CTA overlap hides barrier/staging/poll latency that a single
//        barrier-locked CTA cannot. Per-CTA: 256 thr, 8 warps, 64 units,
//        warp tile 64x32, c-state in SMEM, own-h written straight to SMEM.
// ---------------------------------------------------------------------------

#define LAYERS 50
#define TSTEPS 256
#define GPL    4
#define NCTA   (LAYERS*GPL)                // 200 CTAs, 2 per SM co-resident
#define HSLOT  16384                       // 64*256 halves per time slot
#define HLAYER ((size_t)(TSTEPS+1)*HSLOT)

#define SA_STRIDE 520                      // halves per SMEM A row
#define CB_STRIDE 72                       // floats per cbuf row (64 units)
#define W_WARP_HALVES 16384                // per (l,gg,wn): 32kt*2j*32lane*8h
#define SMEM_BYTES (64*SA_STRIDE*2 + 64*CB_STRIDE*4 + 256*4)   // 86016

__device__ __half   g_h16[(size_t)LAYERS*HLAYER];                 // ~421 MB
__device__ __half   g_w16[(size_t)LAYERS*GPL*8*W_WARP_HALVES];    // ~52 MB
__device__ float    g_bias[LAYERS*1024];
__device__ unsigned g_prog[256];

// ------------------------------- helpers -----------------------------------

__device__ __forceinline__ unsigned long long ld_acq64(const unsigned* p) {
    unsigned long long v;
    asm volatile("ld.acquire.gpu.u64 %0, [%1];" : "=l"(v) : "l"(p) : "memory");
    return v;
}
__device__ __forceinline__ void st_rel(unsigned* p, unsigned v) {
    asm volatile("st.release.gpu.u32 [%0], %1;" :: "l"(p), "r"(v) : "memory");
}
__device__ __forceinline__ void mma16(float* acc, const uint32_t a[4],
                                      uint32_t b0, uint32_t b1) {
    asm("mma.sync.aligned.m16n8k16.row.col.f32.f16.f16.f32 "
        "{%0,%1,%2,%3},{%4,%5,%6,%7},{%8,%9},{%0,%1,%2,%3};"
        : "+f"(acc[0]), "+f"(acc[1]), "+f"(acc[2]), "+f"(acc[3])
        : "r"(a[0]), "r"(a[1]), "r"(a[2]), "r"(a[3]), "r"(b0), "r"(b1));
}
__device__ __forceinline__ void ldsm4(uint32_t r[4], uint32_t saddr) {
    asm volatile("ldmatrix.sync.aligned.m8n8.x4.shared.b16 {%0,%1,%2,%3}, [%4];"
        : "=r"(r[0]), "=r"(r[1]), "=r"(r[2]), "=r"(r[3]) : "r"(saddr));
}
__device__ __forceinline__ float tanhfast(float x) {
    float y;
    asm("tanh.approx.f32 %0, %1;" : "=f"(y) : "f"(x));
    return y;
}
__device__ __forceinline__ float sigm(float x) {          // 1 MUFU
    return fmaf(tanhfast(0.5f * x), 0.5f, 0.5f);
}

// ------------------------------ prep kernels --------------------------------

// Pack weights into uint4-loadable fp16 B fragments, gate-blocked columns.
// half index: [l][gg(4)][wn(8)][kt(32)][j(2)][lane(32)][h(8)]
// CTA gg owns units [64gg, 64gg+64); warp wn owns units [8wn, 8wn+8) of those.
__global__ void prep_wfrag16(const float* __restrict__ Wih,
                             const float* __restrict__ Whh) {
    size_t idx = (size_t)blockIdx.x * 256 + threadIdx.x;
    int h    = (int)(idx & 7);
    int lane = (int)((idx >> 3)  & 31);
    int j    = (int)((idx >> 8)  & 1);
    int kt   = (int)((idx >> 9)  & 31);
    int wn   = (int)((idx >> 14) & 7);
    int gg   = (int)((idx >> 17) & 3);
    int l    = (int)(idx >> 19);
    if (l >= LAYERS) return;
    int jj = h >> 1, hb = h & 1;
    int nt  = j * 2 + (jj >> 1);             // gate 0..3 (i,f,g,o)
    int col = lane >> 2;                     // unit offset 0..7
    int k   = kt * 16 + (lane & 3) * 2 + hb + (jj & 1) * 8;
    int r = nt * 256 + gg * 64 + wn * 8 + col;
    float v = (k < 256) ? Wih[((size_t)l * 1024 + r) * 256 + k]
                        : Whh[((size_t)l * 1024 + r) * 256 + (k - 256)];
    g_w16[idx] = __float2half(v);
}

// sbias[l][gg(4)][wn*32 + nt*8 + cc]
__global__ void prep_bias_init(const float* __restrict__ bih,
                               const float* __restrict__ bhh) {
    int idx = blockIdx.x * 256 + threadIdx.x;
    if (idx < LAYERS * 1024) {
        int l  = idx >> 10;
        int nl = idx & 1023;
        int gg = nl >> 8;
        int nn = nl & 255;
        int wn = nn >> 5;
        int nt = (nn >> 3) & 3;
        int cc = nn & 7;
        int r = nt * 256 + gg * 64 + wn * 8 + cc;
        g_bias[idx] = bih[l * 1024 + r] + bhh[l * 1024 + r];
    }
    if (idx < 256) g_prog[idx] = 0;
}

__global__ void zero_h0() {
    uint4* p = (uint4*)(g_h16 + (size_t)blockIdx.x * HLAYER);  // slot 0
    for (int i = threadIdx.x; i < 2048; i += 256)
        p[i] = make_uint4(0u, 0u, 0u, 0u);
}

// --------------------------- persistent LSTM --------------------------------

#define MMA_BLOCK(B0, B1)                                                     \
    _Pragma("unroll")                                                         \
    for (int mt = 0; mt < 4; ++mt) {                                          \
        mma16(acc[mt][0], av[mt], (B0).x, (B0).y);                            \
        mma16(acc[mt][1], av[mt], (B0).z, (B0).w);                            \
        mma16(acc[mt][2], av[mt], (B1).x, (B1).y);                            \
        mma16(acc[mt][3], av[mt], (B1).z, (B1).w);                            \
    }

__global__ void __launch_bounds__(256, 2)
lstm_persistent(const float* __restrict__ x) {
    extern __shared__ char smem[];
    __half* sA    = (__half*)smem;                                 // 64*520
    float*  cbuf  = (float*)(smem + 64 * SA_STRIDE * 2);           // 64*72
    float*  sbias = (float*)(smem + 64 * SA_STRIDE * 2 + 64 * CB_STRIDE * 4);

    const int l    = blockIdx.x >> 2;
    const int gg   = blockIdx.x & 3;
    const int tid  = threadIdx.x;
    const int lane = tid & 31;
    const int wn   = tid >> 5;      // 0..7 : 8-unit group
    const int q    = lane & 3;

    sbias[tid] = g_bias[(l * GPL + gg) * 256 + tid];
    for (int i = tid; i < 64 * CB_STRIDE; i += 256) cbuf[i] = 0.f;
    // zero own h quarter in sA (h_{-1}=0); peer quarters staged from global
    for (int i = tid; i < 512; i += 256) {
        int row = i >> 3, c8 = i & 7;
        *(uint4*)(sA + row * SA_STRIDE + 256 + gg * 64 + c8 * 8) =
            make_uint4(0u, 0u, 0u, 0u);
    }
    __syncthreads();

    const uint4* wv = (const uint4*)(g_w16 +
        (size_t)((l * GPL + gg) * 8 + wn) * W_WARP_HALVES);
    __half* hlayer = g_h16 + (size_t)l * HLAYER;
    const __half* hprev = (l > 0) ? (g_h16 + (size_t)(l - 1) * HLAYER) : nullptr;

    uint32_t sA_base = (uint32_t)__cvta_generic_to_shared(sA);
    const int rowA = lane & 15;
    const int kofA = (lane >> 4) * 8;

    float acc[4][4][4];        // [mt][gate][frag] : 64 regs

    for (int t = 0; t < TSTEPS; ++t) {
        // ---- wait: all layer peers >= t, all prev-layer CTAs >= t+1 ----
        if (tid == 0) {
            if (t > 0) {
                const unsigned need = (unsigned)t;
                for (;;) {
                    unsigned long long a = ld_acq64(&g_prog[l * 4]);
                    unsigned long long b = ld_acq64(&g_prog[l * 4 + 2]);
                    if ((unsigned)a >= need && (unsigned)(a >> 32) >= need &&
                        (unsigned)b >= need && (unsigned)(b >> 32) >= need)
                        break;
                    __nanosleep(32);
                }
            }
            if (l > 0) {
                const unsigned need = (unsigned)(t + 1);
                for (;;) {
                    unsigned long long a = ld_acq64(&g_prog[(l - 1) * 4]);
                    unsigned long long b = ld_acq64(&g_prog[(l - 1) * 4 + 2]);
                    if ((unsigned)a >= need && (unsigned)(a >> 32) >= need &&
                        (unsigned)b >= need && (unsigned)(b >> 32) >= need)
                        break;
                    __nanosleep(32);
                }
            }
        }
        __syncthreads();

        // ---- stage x_t -> sA[0,256), 3 peer h quarters -> sA[256+pg*64) ----
        if (l == 0) {
            #pragma unroll
            for (int i = tid; i < 4096; i += 256) {       // 64 rows * 64 float4
                int row = i >> 6, c4 = i & 63;
                float4 v = __ldg((const float4*)(x +
                              ((size_t)row * TSTEPS + t) * 256) + c4);
                __half2* dst = (__half2*)(sA + row * SA_STRIDE + c4 * 4);
                dst[0] = __floats2half2_rn(v.x, v.y);
                dst[1] = __floats2half2_rn(v.z, v.w);
            }
        } else {
            const uint4* src = (const uint4*)(hprev + (size_t)(t + 1) * HSLOT);
            #pragma unroll
            for (int i = tid; i < 2048; i += 256) {       // 64 rows * 32 uint4
                int row = i >> 5, c8 = i & 31;
                *(uint4*)(sA + row * SA_STRIDE + c8 * 8) = __ldg(src + i);
            }
        }
        {
            const __half* hsl = hlayer + (size_t)t * HSLOT;
            #pragma unroll
            for (int i = tid; i < 1536; i += 256) {       // 3 * 64 rows * 8 uint4
                int pi  = i >> 9;                          // 0..2
                int pg  = pi + (pi >= gg);                 // skip own quarter
                int rem = i & 511;
                int row = rem >> 3, c8 = rem & 7;
                *(uint4*)(sA + row * SA_STRIDE + 256 + pg * 64 + c8 * 8) =
                    __ldg((const uint4*)(hsl + (size_t)row * 256 + pg * 64) + c8);
            }
        }

        // ---- init accumulators with bias ----
        #pragma unroll
        for (int nt = 0; nt < 4; ++nt) {
            float b0 = sbias[wn * 32 + nt * 8 + q * 2];
            float b1 = sbias[wn * 32 + nt * 8 + q * 2 + 1];
            #pragma unroll
            for (int mt = 0; mt < 4; ++mt) {
                acc[mt][nt][0] = b0; acc[mt][nt][1] = b1;
                acc[mt][nt][2] = b0; acc[mt][nt][3] = b1;
            }
        }
        __syncthreads();

        // ---- GEMM: gates += [x_t | h_{t-1}] @ Wc^T, depth-2 B prefetch ----
        {
            uint4 b0a = __ldg(wv + lane);
            uint4 b0b = __ldg(wv + 32 + lane);
            uint4 b1a = __ldg(wv + 64 + lane);
            uint4 b1b = __ldg(wv + 96 + lane);
            #pragma unroll 4
            for (int kt = 0; kt < 32; ++kt) {
                uint32_t av[4][4];
                #pragma unroll
                for (int mt = 0; mt < 4; ++mt) {
                    uint32_t addr = sA_base + (uint32_t)(
                        ((mt * 16 + rowA) * SA_STRIDE + kt * 16 + kofA) * 2);
                    ldsm4(av[mt], addr);
                }
                uint4 na, nb;
                if (kt < 30) {
                    na = __ldg(wv + (kt + 2) * 64 + lane);
                    nb = __ldg(wv + (kt + 2) * 64 + 32 + lane);
                }
                if (kt & 1) {
                    MMA_BLOCK(b1a, b1b)
                    if (kt < 30) { b1a = na; b1b = nb; }
                } else {
                    MMA_BLOCK(b0a, b0b)
                    if (kt < 30) { b0a = na; b0b = nb; }
                }
            }
        }
        __syncthreads();   // all LDSM done before sA h-region is rewritten

        // ---- elementwise LSTM update (tanh.approx, c in SMEM) ----
        // element (mt,j): row = mt*16 + (lane>>2) + (j>>1)*8,
        // local unit u0 = wn*8 + 2q + (j&1); gates acc[mt][0..3][j] = i,f,g,o
        __half* houtg = hlayer + (size_t)(t + 1) * HSLOT + gg * 64;
        __half* houts = sA + 256 + gg * 64;
        const int rbase = lane >> 2;
        const int u0 = wn * 8 + 2 * q;
        #pragma unroll
        for (int mt = 0; mt < 4; ++mt) {
            int row0 = mt * 16 + rbase;
            float2 c01 = *(float2*)&cbuf[row0 * CB_STRIDE + u0];
            float2 c23 = *(float2*)&cbuf[(row0 + 8) * CB_STRIDE + u0];
            float cv[4] = {c01.x, c01.y, c23.x, c23.y};
            float hv[4];
            #pragma unroll
            for (int j = 0; j < 4; ++j) {
                float i_ = sigm(acc[mt][0][j]);
                float f_ = sigm(acc[mt][1][j]);
                float g_ = tanhfast(acc[mt][2][j]);
                float o_ = sigm(acc[mt][3][j]);
                float cn = fmaf(f_, cv[j], i_ * g_);
                cv[j] = cn;
                hv[j] = o_ * tanhfast(cn);
            }
            *(float2*)&cbuf[row0 * CB_STRIDE + u0]       = make_float2(cv[0], cv[1]);
            *(float2*)&cbuf[(row0 + 8) * CB_STRIDE + u0] = make_float2(cv[2], cv[3]);
            __half2 h01 = __floats2half2_rn(hv[0], hv[1]);
            __half2 h23 = __floats2half2_rn(hv[2], hv[3]);
            *(__half2*)(houtg + (size_t)row0 * 256 + u0)       = h01;
            *(__half2*)(houtg + (size_t)(row0 + 8) * 256 + u0) = h23;
            *(__half2*)(houts + row0 * SA_STRIDE + u0)         = h01;
            *(__half2*)(houts + (row0 + 8) * SA_STRIDE + u0)   = h23;
        }

        __syncthreads();
        if (tid == 0) st_rel(&g_prog[l * GPL + gg], (unsigned)(t + 1));
    }
}

// ------------------------------ output head ---------------------------------

__global__ void out_proj(const float* __restrict__ Wout,
                         const float* __restrict__ bout,
                         float* __restrict__ out) {
    int p = blockIdx.x * 8 + (threadIdx.x >> 5);   // (t*64+b), 16384 total
    int lane = threadIdx.x & 31;
    int t = p >> 6, b = p & 63;
    const __half* h = g_h16 + (size_t)(LAYERS - 1) * HLAYER +
                      (size_t)(t + 1) * HSLOT + (size_t)b * 256 + lane * 8;
    uint4 hv = *(const uint4*)h;
    const __half2* hh = (const __half2*)&hv;
    const float* w0 = Wout + lane * 8;
    const float* w1 = Wout + 256 + lane * 8;
    float s0 = 0.f, s1 = 0.f;
    #pragma unroll
    for (int j = 0; j < 4; ++j) {
        float2 f = __half22float2(hh[j]);
        s0 += f.x * w0[2 * j] + f.y * w0[2 * j + 1];
        s1 += f.x * w1[2 * j] + f.y * w1[2 * j + 1];
    }
    #pragma unroll
    for (int off = 16; off > 0; off >>= 1) {
        s0 += __shfl_xor_sync(0xffffffffu, s0, off);
        s1 += __shfl_xor_sync(0xffffffffu, s1, off);
    }
    if (lane == 0) {
        float e0 = __expf(-(s0 + bout[0]));
        float e1 = __expf(-(s1 + bout[1]));
        out[(size_t)b * (TSTEPS * 2) + t * 2 + 0] = __fdividef(1.f, 1.f + e0);
        out[(size_t)b * (TSTEPS * 2) + t * 2 + 1] = __fdividef(1.f, 1.f + e1);
    }
}

// ------------------------------- launcher -----------------------------------

extern "C" void kernel_launch(void* const* d_in, const int* in_sizes, int n_in,
                              void* d_out, int out_size) {
    const float* x    = (const float*)d_in[0];
    const float* Wih  = (const float*)d_in[1];
    const float* Whh  = (const float*)d_in[2];
    const float* bih  = (const float*)d_in[3];
    const float* bhh  = (const float*)d_in[4];
    const float* Wout = (const float*)d_in[5];
    const float* bout = (const float*)d_in[6];
    float* out = (float*)d_out;

    cudaFuncSetAttribute(lstm_persistent,
                         cudaFuncAttributeMaxDynamicSharedMemorySize, SMEM_BYTES);

    prep_wfrag16<<<102400, 256>>>(Wih, Whh);    // 26.2M packed fp16 fragments
    prep_bias_init<<<200, 256>>>(bih, bhh);     // bias permute + progress reset
    zero_h0<<<LAYERS, 256>>>();                 // h_{-1} = 0 slots (fp16)
    lstm_persistent<<<NCTA, 256, SMEM_BYTES>>>(x);
    out_proj<<<2048, 256>>>(Wout, bout, out);   // final sigmoid head
}